// round 4
// baseline (speedup 1.0000x reference)
#include <cuda_runtime.h>
#include <cstdint>

#define B_    8
#define CIN_  512
#define COUT_ 1024
#define P_    2048
#define H_    8
#define DH_   128
#define NBH_  64
#define EPS_  1e-5f

// ---------------- scratch (device globals; no allocation) ----------------
__device__ float g_Y[3][(size_t)B_ * COUT_ * P_];     // raw projections q/k/v
__device__ float g_E[(size_t)NBH_ * P_ * P_];         // exp(logits)  [bh][i][j]
__device__ float g_a[3][COUT_];                       // BN scale
__device__ float g_bsh[3][COUT_];                     // BN shift
__device__ float g_rsinv[NBH_ * P_];                  // 1 / softmax row sums

__device__ __forceinline__ float lrelu(float v) { return fmaxf(v, 0.1f * v); }

// ====================================================================
// Stage 1: projections.  Y[proj][b][o][p] = sum_c W[o][c] * x[b][c][p]
// 128x128 tile, BK=8, 256 threads, 8x8 microtile.
// grid: (16 ptiles, 8 otiles, 24 = proj*8+b)
// ====================================================================
__global__ __launch_bounds__(256) void proj_kernel(
    const float* __restrict__ x,
    const float* __restrict__ Wq,
    const float* __restrict__ Wk,
    const float* __restrict__ Wv)
{
    const int proj = blockIdx.z >> 3;
    const int b    = blockIdx.z & 7;
    const float* W = (proj == 0) ? Wq : ((proj == 1) ? Wk : Wv);
    const float* X = x + (size_t)b * CIN_ * P_;
    float* Y       = g_Y[proj] + (size_t)b * COUT_ * P_;
    const int m0 = blockIdx.y * 128;
    const int n0 = blockIdx.x * 128;

    __shared__ __align__(16) float As[8][128];
    __shared__ __align__(16) float Bs[8][128];

    const int t  = threadIdx.x;
    const int tx = t & 15, ty = t >> 4;

    float acc[8][8];
#pragma unroll
    for (int i = 0; i < 8; i++)
#pragma unroll
        for (int j = 0; j < 8; j++) acc[i][j] = 0.0f;

    const int am = t & 127, ak = (t >> 7) << 2;   // A: row m, 4 consecutive k
    const int bk = t >> 5,  bn = (t & 31) << 2;   // B: row k, 4 consecutive n

    for (int k0 = 0; k0 < CIN_; k0 += 8) {
        float4 av = *(const float4*)&W[(size_t)(m0 + am) * CIN_ + k0 + ak];
        float4 bv = *(const float4*)&X[(size_t)(k0 + bk) * P_ + n0 + bn];
        __syncthreads();
        As[ak + 0][am] = av.x; As[ak + 1][am] = av.y;
        As[ak + 2][am] = av.z; As[ak + 3][am] = av.w;
        *(float4*)&Bs[bk][bn] = bv;
        __syncthreads();
#pragma unroll
        for (int kk = 0; kk < 8; kk++) {
            float a[8], bb[8];
            *(float4*)&a[0]  = *(const float4*)&As[kk][ty * 8];
            *(float4*)&a[4]  = *(const float4*)&As[kk][ty * 8 + 4];
            *(float4*)&bb[0] = *(const float4*)&Bs[kk][tx * 8];
            *(float4*)&bb[4] = *(const float4*)&Bs[kk][tx * 8 + 4];
#pragma unroll
            for (int i = 0; i < 8; i++)
#pragma unroll
                for (int j = 0; j < 8; j++)
                    acc[i][j] = fmaf(a[i], bb[j], acc[i][j]);
        }
    }

#pragma unroll
    for (int i = 0; i < 8; i++) {
        const int m = ty * 8 + i;
        float4 o0 = make_float4(acc[i][0], acc[i][1], acc[i][2], acc[i][3]);
        float4 o1 = make_float4(acc[i][4], acc[i][5], acc[i][6], acc[i][7]);
        *(float4*)&Y[(size_t)(m0 + m) * P_ + n0 + tx * 8]     = o0;
        *(float4*)&Y[(size_t)(m0 + m) * P_ + n0 + tx * 8 + 4] = o1;
    }
}

// ====================================================================
// Stage 2: deterministic per-channel BN stats -> affine params.
// grid: (1024 channels, 3 projs), 256 threads per block.
// ====================================================================
__global__ __launch_bounds__(256) void stats_kernel(
    const float* __restrict__ gq, const float* __restrict__ bq,
    const float* __restrict__ gk, const float* __restrict__ bk,
    const float* __restrict__ gv, const float* __restrict__ bv)
{
    const int proj = blockIdx.y;
    const int ch   = blockIdx.x;
    const int t    = threadIdx.x;
    const float* Ych = g_Y[proj] + (size_t)ch * P_;

    float s = 0.0f, q = 0.0f;
    for (int b = 0; b < B_; b++) {
        const float* row = Ych + (size_t)b * COUT_ * P_;
        for (int p = t * 4; p < P_; p += 1024) {
            float4 v = *(const float4*)&row[p];
            s += v.x + v.y + v.z + v.w;
            q = fmaf(v.x, v.x, q); q = fmaf(v.y, v.y, q);
            q = fmaf(v.z, v.z, q); q = fmaf(v.w, v.w, q);
        }
    }
    __shared__ float rs[256], rq[256];
    rs[t] = s; rq[t] = q;
    __syncthreads();
    for (int st = 128; st > 0; st >>= 1) {
        if (t < st) { rs[t] += rs[t + st]; rq[t] += rq[t + st]; }
        __syncthreads();
    }
    if (t == 0) {
        const float n    = (float)(B_ * P_);
        const float mean = rs[0] / n;
        const float var  = rq[0] / n - mean * mean;
        const float* g  = (proj == 0) ? gq : ((proj == 1) ? gk : gv);
        const float* be = (proj == 0) ? bq : ((proj == 1) ? bk : bv);
        const float a = g[ch] * rsqrtf(var + EPS_);
        g_a[proj][ch]   = a;
        g_bsh[proj][ch] = be[ch] - mean * a;
    }
}

// ====================================================================
// Stage 3: E[bh][i][j] = exp( (1/sqrt(128)) * sum_c Kt[c][i]*Vt[c][j] )
// where Kt/Vt = lrelu(BN(Yk/Yv)) applied on load.  128x128 tile, K=128.
// grid: (16 jtiles, 16 itiles, 64 bh)
// ====================================================================
__global__ __launch_bounds__(256) void attnE_kernel()
{
    const int bh = blockIdx.z;
    const int b  = bh >> 3, h = bh & 7;
    const int i0 = blockIdx.y * 128;
    const int j0 = blockIdx.x * 128;
    const float* YK = g_Y[1] + (size_t)b * COUT_ * P_ + (size_t)(h * DH_) * P_;
    const float* YV = g_Y[2] + (size_t)b * COUT_ * P_ + (size_t)(h * DH_) * P_;

    __shared__ __align__(16) float As[8][128];
    __shared__ __align__(16) float Bs[8][128];
    __shared__ float ska[128], skb[128], sva[128], svb[128];

    const int t  = threadIdx.x;
    const int tx = t & 15, ty = t >> 4;
    if (t < 128) {
        ska[t] = g_a[1][h * DH_ + t];  skb[t] = g_bsh[1][h * DH_ + t];
        sva[t] = g_a[2][h * DH_ + t];  svb[t] = g_bsh[2][h * DH_ + t];
    }
    __syncthreads();

    float acc[8][8];
#pragma unroll
    for (int i = 0; i < 8; i++)
#pragma unroll
        for (int j = 0; j < 8; j++) acc[i][j] = 0.0f;

    const int lk = t >> 5, ln = (t & 31) << 2;

    for (int c0 = 0; c0 < DH_; c0 += 8) {
        const int ck = c0 + lk;
        float4 kv = *(const float4*)&YK[(size_t)ck * P_ + i0 + ln];
        float4 vv = *(const float4*)&YV[(size_t)ck * P_ + j0 + ln];
        const float ka = ska[ck], kb2 = skb[ck];
        const float va = sva[ck], vb2 = svb[ck];
        kv.x = lrelu(fmaf(ka, kv.x, kb2)); kv.y = lrelu(fmaf(ka, kv.y, kb2));
        kv.z = lrelu(fmaf(ka, kv.z, kb2)); kv.w = lrelu(fmaf(ka, kv.w, kb2));
        vv.x = lrelu(fmaf(va, vv.x, vb2)); vv.y = lrelu(fmaf(va, vv.y, vb2));
        vv.z = lrelu(fmaf(va, vv.z, vb2)); vv.w = lrelu(fmaf(va, vv.w, vb2));
        __syncthreads();
        *(float4*)&As[lk][ln] = kv;
        *(float4*)&Bs[lk][ln] = vv;
        __syncthreads();
#pragma unroll
        for (int kk = 0; kk < 8; kk++) {
            float a[8], bb[8];
            *(float4*)&a[0]  = *(const float4*)&As[kk][ty * 8];
            *(float4*)&a[4]  = *(const float4*)&As[kk][ty * 8 + 4];
            *(float4*)&bb[0] = *(const float4*)&Bs[kk][tx * 8];
            *(float4*)&bb[4] = *(const float4*)&Bs[kk][tx * 8 + 4];
#pragma unroll
            for (int i = 0; i < 8; i++)
#pragma unroll
                for (int j = 0; j < 8; j++)
                    acc[i][j] = fmaf(a[i], bb[j], acc[i][j]);
        }
    }

    const float scale = 0.08838834764831845f;  // 1/sqrt(128)
    float* E = g_E + (size_t)bh * P_ * P_;
#pragma unroll
    for (int i = 0; i < 8; i++) {
        const int m = ty * 8 + i;
        float4 e0, e1;
        e0.x = __expf(acc[i][0] * scale); e0.y = __expf(acc[i][1] * scale);
        e0.z = __expf(acc[i][2] * scale); e0.w = __expf(acc[i][3] * scale);
        e1.x = __expf(acc[i][4] * scale); e1.y = __expf(acc[i][5] * scale);
        e1.z = __expf(acc[i][6] * scale); e1.w = __expf(acc[i][7] * scale);
        *(float4*)&E[(size_t)(i0 + m) * P_ + j0 + tx * 8]     = e0;
        *(float4*)&E[(size_t)(i0 + m) * P_ + j0 + tx * 8 + 4] = e1;
    }
}

// ====================================================================
// Stage 4: deterministic softmax denominators: g_rsinv[r] = 1/sum_j E[r][j]
// one block per row, 256 threads. grid: 64*2048 blocks.
// ====================================================================
__global__ __launch_bounds__(256) void rowsum_kernel()
{
    const size_t r = blockIdx.x;
    const float* row = g_E + r * (size_t)P_;
    const int t = threadIdx.x;
    float4 v0 = *(const float4*)&row[t * 8];
    float4 v1 = *(const float4*)&row[t * 8 + 4];
    float s = v0.x + v0.y + v0.z + v0.w + v1.x + v1.y + v1.z + v1.w;
    __shared__ float red[256];
    red[t] = s;
    __syncthreads();
    for (int st = 128; st > 0; st >>= 1) {
        if (t < st) red[t] += red[t + st];
        __syncthreads();
    }
    if (t == 0) g_rsinv[r] = 1.0f / red[0];
}

// ====================================================================
// Stage 5: out[b][h*128+c][i] = rsinv[i] * sum_j Qt[c][j] * E[i][j]
// Qt = lrelu(BN(Yq)).  M=128(c), N=128(i) tile, K=2048(j), BK=8.
// grid: (16 itiles, 1, 64 bh)
// ====================================================================
__global__ __launch_bounds__(256) void out_kernel(float* __restrict__ out)
{
    const int bh = blockIdx.z;
    const int b  = bh >> 3, h = bh & 7;
    const int n0 = blockIdx.x * 128;
    const float* YQ = g_Y[0] + (size_t)b * COUT_ * P_ + (size_t)(h * DH_) * P_;
    const float* E  = g_E + (size_t)bh * P_ * P_;

    __shared__ __align__(16) float As[8][128];
    __shared__ __align__(16) float Bs[8][128];

    const int t  = threadIdx.x;
    const int tx = t & 15, ty = t >> 4;
    const int lm = t & 127, lk4 = (t >> 7) << 2;

    const float qa = g_a[0][h * DH_ + lm];
    const float qb = g_bsh[0][h * DH_ + lm];

    float acc[8][8];
#pragma unroll
    for (int i = 0; i < 8; i++)
#pragma unroll
        for (int j = 0; j < 8; j++) acc[i][j] = 0.0f;

    for (int j0 = 0; j0 < P_; j0 += 8) {
        float4 qv = *(const float4*)&YQ[(size_t)lm * P_ + j0 + lk4];
        float4 ev = *(const float4*)&E[(size_t)(n0 + lm) * P_ + j0 + lk4];
        qv.x = lrelu(fmaf(qa, qv.x, qb)); qv.y = lrelu(fmaf(qa, qv.y, qb));
        qv.z = lrelu(fmaf(qa, qv.z, qb)); qv.w = lrelu(fmaf(qa, qv.w, qb));
        __syncthreads();
        As[lk4 + 0][lm] = qv.x; As[lk4 + 1][lm] = qv.y;
        As[lk4 + 2][lm] = qv.z; As[lk4 + 3][lm] = qv.w;
        Bs[lk4 + 0][lm] = ev.x; Bs[lk4 + 1][lm] = ev.y;
        Bs[lk4 + 2][lm] = ev.z; Bs[lk4 + 3][lm] = ev.w;
        __syncthreads();
#pragma unroll
        for (int kk = 0; kk < 8; kk++) {
            float a[8], bb[8];
            *(float4*)&a[0]  = *(const float4*)&As[kk][ty * 8];
            *(float4*)&a[4]  = *(const float4*)&As[kk][ty * 8 + 4];
            *(float4*)&bb[0] = *(const float4*)&Bs[kk][tx * 8];
            *(float4*)&bb[4] = *(const float4*)&Bs[kk][tx * 8 + 4];
#pragma unroll
            for (int i = 0; i < 8; i++)
#pragma unroll
                for (int j = 0; j < 8; j++)
                    acc[i][j] = fmaf(a[i], bb[j], acc[i][j]);
        }
    }

    float inv[8];
#pragma unroll
    for (int j = 0; j < 8; j++)
        inv[j] = g_rsinv[bh * P_ + n0 + tx * 8 + j];

#pragma unroll
    for (int i = 0; i < 8; i++) {
        const int m = ty * 8 + i;  // c within head
        float4 o0 = make_float4(acc[i][0] * inv[0], acc[i][1] * inv[1],
                                acc[i][2] * inv[2], acc[i][3] * inv[3]);
        float4 o1 = make_float4(acc[i][4] * inv[4], acc[i][5] * inv[5],
                                acc[i][6] * inv[6], acc[i][7] * inv[7]);
        float* orow = out + (size_t)b * COUT_ * P_ + (size_t)(h * DH_ + m) * P_;
        *(float4*)&orow[n0 + tx * 8]     = o0;
        *(float4*)&orow[n0 + tx * 8 + 4] = o1;
    }
}

// ====================================================================
extern "C" void kernel_launch(void* const* d_in, const int* in_sizes, int n_in,
                              void* d_out, int out_size)
{
    const float* x  = (const float*)d_in[0];
    const float* Wq = (const float*)d_in[1];
    const float* gq = (const float*)d_in[2];
    const float* bq = (const float*)d_in[3];
    const float* Wk = (const float*)d_in[4];
    const float* gk = (const float*)d_in[5];
    const float* bk = (const float*)d_in[6];
    const float* Wv = (const float*)d_in[7];
    const float* gv = (const float*)d_in[8];
    const float* bv = (const float*)d_in[9];
    float* out = (float*)d_out;

    proj_kernel  <<< dim3(16, 8, 24), 256 >>>(x, Wq, Wk, Wv);
    stats_kernel <<< dim3(COUT_, 3, 1), 256 >>>(gq, bq, gk, bk, gv, bv);
    attnE_kernel <<< dim3(16, 16, NBH_), 256 >>>();
    rowsum_kernel<<< NBH_ * P_, 256 >>>();
    out_kernel   <<< dim3(16, 1, NBH_), 256 >>>(out);
}

// round 6
// speedup vs baseline: 1.0009x; 1.0009x over previous
#include <cuda_runtime.h>
#include <cstdint>

#define B_    8
#define CIN_  512
#define COUT_ 1024
#define P_    2048
#define H_    8
#define DH_   128
#define NBH_  64
#define EPS_  1e-5f

// ---------------- scratch (device globals; no allocation) ----------------
__device__ float g_Y[3][(size_t)B_ * COUT_ * P_];     // raw projections q/k/v
__device__ float g_E[(size_t)NBH_ * P_ * P_];         // exp(logits)  [bh][i][j]
__device__ float g_a[3][COUT_];                       // BN scale
__device__ float g_bsh[3][COUT_];                     // BN shift
__device__ float g_rsinv[NBH_ * P_];                  // 1 / softmax row sums

__device__ __forceinline__ float lrelu(float v) { return fmaxf(v, 0.1f * v); }

// ====================================================================
// Stage 1: projections.  Y[proj][b][o][p] = sum_c W[o][c] * x[b][c][p]
// 128x128 tile, BK=8, 256 threads, 8x8 microtile.
// grid: (16 ptiles, 8 otiles, 24 = proj*8+b)
// ====================================================================
__global__ __launch_bounds__(256) void proj_kernel(
    const float* __restrict__ x,
    const float* __restrict__ Wq,
    const float* __restrict__ Wk,
    const float* __restrict__ Wv)
{
    const int proj = blockIdx.z >> 3;
    const int b    = blockIdx.z & 7;
    const float* W = (proj == 0) ? Wq : ((proj == 1) ? Wk : Wv);
    const float* X = x + (size_t)b * CIN_ * P_;
    float* Y       = g_Y[proj] + (size_t)b * COUT_ * P_;
    const int m0 = blockIdx.y * 128;
    const int n0 = blockIdx.x * 128;

    __shared__ __align__(16) float As[8][128];
    __shared__ __align__(16) float Bs[8][128];

    const int t  = threadIdx.x;
    const int tx = t & 15, ty = t >> 4;

    float acc[8][8];
#pragma unroll
    for (int i = 0; i < 8; i++)
#pragma unroll
        for (int j = 0; j < 8; j++) acc[i][j] = 0.0f;

    const int am = t & 127, ak = (t >> 7) << 2;   // A: row m, 4 consecutive k
    const int bk = t >> 5,  bn = (t & 31) << 2;   // B: row k, 4 consecutive n

    for (int k0 = 0; k0 < CIN_; k0 += 8) {
        float4 av = *(const float4*)&W[(size_t)(m0 + am) * CIN_ + k0 + ak];
        float4 bv = *(const float4*)&X[(size_t)(k0 + bk) * P_ + n0 + bn];
        __syncthreads();
        As[ak + 0][am] = av.x; As[ak + 1][am] = av.y;
        As[ak + 2][am] = av.z; As[ak + 3][am] = av.w;
        *(float4*)&Bs[bk][bn] = bv;
        __syncthreads();
#pragma unroll
        for (int kk = 0; kk < 8; kk++) {
            float a[8], bb[8];
            *(float4*)&a[0]  = *(const float4*)&As[kk][ty * 8];
            *(float4*)&a[4]  = *(const float4*)&As[kk][ty * 8 + 4];
            *(float4*)&bb[0] = *(const float4*)&Bs[kk][tx * 8];
            *(float4*)&bb[4] = *(const float4*)&Bs[kk][tx * 8 + 4];
#pragma unroll
            for (int i = 0; i < 8; i++)
#pragma unroll
                for (int j = 0; j < 8; j++)
                    acc[i][j] = fmaf(a[i], bb[j], acc[i][j]);
        }
    }

#pragma unroll
    for (int i = 0; i < 8; i++) {
        const int m = ty * 8 + i;
        float4 o0 = make_float4(acc[i][0], acc[i][1], acc[i][2], acc[i][3]);
        float4 o1 = make_float4(acc[i][4], acc[i][5], acc[i][6], acc[i][7]);
        *(float4*)&Y[(size_t)(m0 + m) * P_ + n0 + tx * 8]     = o0;
        *(float4*)&Y[(size_t)(m0 + m) * P_ + n0 + tx * 8 + 4] = o1;
    }
}

// ====================================================================
// Stage 2: deterministic per-channel BN stats -> affine params.
// grid: (1024 channels, 3 projs), 256 threads per block.
// ====================================================================
__global__ __launch_bounds__(256) void stats_kernel(
    const float* __restrict__ gq, const float* __restrict__ bq,
    const float* __restrict__ gk, const float* __restrict__ bk,
    const float* __restrict__ gv, const float* __restrict__ bv)
{
    const int proj = blockIdx.y;
    const int ch   = blockIdx.x;
    const int t    = threadIdx.x;
    const float* Ych = g_Y[proj] + (size_t)ch * P_;

    float s = 0.0f, q = 0.0f;
    for (int b = 0; b < B_; b++) {
        const float* row = Ych + (size_t)b * COUT_ * P_;
        for (int p = t * 4; p < P_; p += 1024) {
            float4 v = *(const float4*)&row[p];
            s += v.x + v.y + v.z + v.w;
            q = fmaf(v.x, v.x, q); q = fmaf(v.y, v.y, q);
            q = fmaf(v.z, v.z, q); q = fmaf(v.w, v.w, q);
        }
    }
    __shared__ float rs[256], rq[256];
    rs[t] = s; rq[t] = q;
    __syncthreads();
    for (int st = 128; st > 0; st >>= 1) {
        if (t < st) { rs[t] += rs[t + st]; rq[t] += rq[t + st]; }
        __syncthreads();
    }
    if (t == 0) {
        const float n    = (float)(B_ * P_);
        const float mean = rs[0] / n;
        const float var  = rq[0] / n - mean * mean;
        const float* g  = (proj == 0) ? gq : ((proj == 1) ? gk : gv);
        const float* be = (proj == 0) ? bq : ((proj == 1) ? bk : bv);
        const float a = g[ch] * rsqrtf(var + EPS_);
        g_a[proj][ch]   = a;
        g_bsh[proj][ch] = be[ch] - mean * a;
    }
}

// ====================================================================
// Stage 3: E[bh][i][j] = exp( (1/sqrt(128)) * sum_c Kt[c][i]*Vt[c][j] )
// where Kt/Vt = lrelu(BN(Yk/Yv)) applied on load.  128x128 tile, K=128.
// grid: (16 jtiles, 16 itiles, 64 bh)
// ====================================================================
__global__ __launch_bounds__(256) void attnE_kernel()
{
    const int bh = blockIdx.z;
    const int b  = bh >> 3, h = bh & 7;
    const int i0 = blockIdx.y * 128;
    const int j0 = blockIdx.x * 128;
    const float* YK = g_Y[1] + (size_t)b * COUT_ * P_ + (size_t)(h * DH_) * P_;
    const float* YV = g_Y[2] + (size_t)b * COUT_ * P_ + (size_t)(h * DH_) * P_;

    __shared__ __align__(16) float As[8][128];
    __shared__ __align__(16) float Bs[8][128];
    __shared__ float ska[128], skb[128], sva[128], svb[128];

    const int t  = threadIdx.x;
    const int tx = t & 15, ty = t >> 4;
    if (t < 128) {
        ska[t] = g_a[1][h * DH_ + t];  skb[t] = g_bsh[1][h * DH_ + t];
        sva[t] = g_a[2][h * DH_ + t];  svb[t] = g_bsh[2][h * DH_ + t];
    }
    __syncthreads();

    float acc[8][8];
#pragma unroll
    for (int i = 0; i < 8; i++)
#pragma unroll
        for (int j = 0; j < 8; j++) acc[i][j] = 0.0f;

    const int lk = t >> 5, ln = (t & 31) << 2;

    for (int c0 = 0; c0 < DH_; c0 += 8) {
        const int ck = c0 + lk;
        float4 kv = *(const float4*)&YK[(size_t)ck * P_ + i0 + ln];
        float4 vv = *(const float4*)&YV[(size_t)ck * P_ + j0 + ln];
        const float ka = ska[ck], kb2 = skb[ck];
        const float va = sva[ck], vb2 = svb[ck];
        kv.x = lrelu(fmaf(ka, kv.x, kb2)); kv.y = lrelu(fmaf(ka, kv.y, kb2));
        kv.z = lrelu(fmaf(ka, kv.z, kb2)); kv.w = lrelu(fmaf(ka, kv.w, kb2));
        vv.x = lrelu(fmaf(va, vv.x, vb2)); vv.y = lrelu(fmaf(va, vv.y, vb2));
        vv.z = lrelu(fmaf(va, vv.z, vb2)); vv.w = lrelu(fmaf(va, vv.w, vb2));
        __syncthreads();
        *(float4*)&As[lk][ln] = kv;
        *(float4*)&Bs[lk][ln] = vv;
        __syncthreads();
#pragma unroll
        for (int kk = 0; kk < 8; kk++) {
            float a[8], bb[8];
            *(float4*)&a[0]  = *(const float4*)&As[kk][ty * 8];
            *(float4*)&a[4]  = *(const float4*)&As[kk][ty * 8 + 4];
            *(float4*)&bb[0] = *(const float4*)&Bs[kk][tx * 8];
            *(float4*)&bb[4] = *(const float4*)&Bs[kk][tx * 8 + 4];
#pragma unroll
            for (int i = 0; i < 8; i++)
#pragma unroll
                for (int j = 0; j < 8; j++)
                    acc[i][j] = fmaf(a[i], bb[j], acc[i][j]);
        }
    }

    const float scale = 0.08838834764831845f;  // 1/sqrt(128)
    float* E = g_E + (size_t)bh * P_ * P_;
#pragma unroll
    for (int i = 0; i < 8; i++) {
        const int m = ty * 8 + i;
        float4 e0, e1;
        e0.x = __expf(acc[i][0] * scale); e0.y = __expf(acc[i][1] * scale);
        e0.z = __expf(acc[i][2] * scale); e0.w = __expf(acc[i][3] * scale);
        e1.x = __expf(acc[i][4] * scale); e1.y = __expf(acc[i][5] * scale);
        e1.z = __expf(acc[i][6] * scale); e1.w = __expf(acc[i][7] * scale);
        *(float4*)&E[(size_t)(i0 + m) * P_ + j0 + tx * 8]     = e0;
        *(float4*)&E[(size_t)(i0 + m) * P_ + j0 + tx * 8 + 4] = e1;
    }
}

// ====================================================================
// Stage 4: deterministic softmax denominators: g_rsinv[r] = 1/sum_j E[r][j]
// one block per row, 256 threads. grid: 64*2048 blocks.
// ====================================================================
__global__ __launch_bounds__(256) void rowsum_kernel()
{
    const size_t r = blockIdx.x;
    const float* row = g_E + r * (size_t)P_;
    const int t = threadIdx.x;
    float4 v0 = *(const float4*)&row[t * 8];
    float4 v1 = *(const float4*)&row[t * 8 + 4];
    float s = v0.x + v0.y + v0.z + v0.w + v1.x + v1.y + v1.z + v1.w;
    __shared__ float red[256];
    red[t] = s;
    __syncthreads();
    for (int st = 128; st > 0; st >>= 1) {
        if (t < st) red[t] += red[t + st];
        __syncthreads();
    }
    if (t == 0) g_rsinv[r] = 1.0f / red[0];
}

// ====================================================================
// Stage 5: out[b][h*128+c][i] = rsinv[i] * sum_j Qt[c][j] * E[i][j]
// Qt = lrelu(BN(Yq)).  M=128(c), N=128(i) tile, K=2048(j), BK=8.
// grid: (16 itiles, 1, 64 bh)
// ====================================================================
__global__ __launch_bounds__(256) void out_kernel(float* __restrict__ out)
{
    const int bh = blockIdx.z;
    const int b  = bh >> 3, h = bh & 7;
    const int n0 = blockIdx.x * 128;
    const float* YQ = g_Y[0] + (size_t)b * COUT_ * P_ + (size_t)(h * DH_) * P_;
    const float* E  = g_E + (size_t)bh * P_ * P_;

    __shared__ __align__(16) float As[8][128];
    __shared__ __align__(16) float Bs[8][128];

    const int t  = threadIdx.x;
    const int tx = t & 15, ty = t >> 4;
    const int lm = t & 127, lk4 = (t >> 7) << 2;

    const float qa = g_a[0][h * DH_ + lm];
    const float qb = g_bsh[0][h * DH_ + lm];

    float acc[8][8];
#pragma unroll
    for (int i = 0; i < 8; i++)
#pragma unroll
        for (int j = 0; j < 8; j++) acc[i][j] = 0.0f;

    for (int j0 = 0; j0 < P_; j0 += 8) {
        float4 qv = *(const float4*)&YQ[(size_t)lm * P_ + j0 + lk4];
        float4 ev = *(const float4*)&E[(size_t)(n0 + lm) * P_ + j0 + lk4];
        qv.x = lrelu(fmaf(qa, qv.x, qb)); qv.y = lrelu(fmaf(qa, qv.y, qb));
        qv.z = lrelu(fmaf(qa, qv.z, qb)); qv.w = lrelu(fmaf(qa, qv.w, qb));
        __syncthreads();
        As[lk4 + 0][lm] = qv.x; As[lk4 + 1][lm] = qv.y;
        As[lk4 + 2][lm] = qv.z; As[lk4 + 3][lm] = qv.w;
        Bs[lk4 + 0][lm] = ev.x; Bs[lk4 + 1][lm] = ev.y;
        Bs[lk4 + 2][lm] = ev.z; Bs[lk4 + 3][lm] = ev.w;
        __syncthreads();
#pragma unroll
        for (int kk = 0; kk < 8; kk++) {
            float a[8], bb[8];
            *(float4*)&a[0]  = *(const float4*)&As[kk][ty * 8];
            *(float4*)&a[4]  = *(const float4*)&As[kk][ty * 8 + 4];
            *(float4*)&bb[0] = *(const float4*)&Bs[kk][tx * 8];
            *(float4*)&bb[4] = *(const float4*)&Bs[kk][tx * 8 + 4];
#pragma unroll
            for (int i = 0; i < 8; i++)
#pragma unroll
                for (int j = 0; j < 8; j++)
                    acc[i][j] = fmaf(a[i], bb[j], acc[i][j]);
        }
    }

    float inv[8];
#pragma unroll
    for (int j = 0; j < 8; j++)
        inv[j] = g_rsinv[bh * P_ + n0 + tx * 8 + j];

#pragma unroll
    for (int i = 0; i < 8; i++) {
        const int m = ty * 8 + i;  // c within head
        float4 o0 = make_float4(acc[i][0] * inv[0], acc[i][1] * inv[1],
                                acc[i][2] * inv[2], acc[i][3] * inv[3]);
        float4 o1 = make_float4(acc[i][4] * inv[4], acc[i][5] * inv[5],
                                acc[i][6] * inv[6], acc[i][7] * inv[7]);
        float* orow = out + (size_t)b * COUT_ * P_ + (size_t)(h * DH_ + m) * P_;
        *(float4*)&orow[n0 + tx * 8]     = o0;
        *(float4*)&orow[n0 + tx * 8 + 4] = o1;
    }
}

// ====================================================================
extern "C" void kernel_launch(void* const* d_in, const int* in_sizes, int n_in,
                              void* d_out, int out_size)
{
    const float* x  = (const float*)d_in[0];
    const float* Wq = (const float*)d_in[1];
    const float* gq = (const float*)d_in[2];
    const float* bq = (const float*)d_in[3];
    const float* Wk = (const float*)d_in[4];
    const float* gk = (const float*)d_in[5];
    const float* bk = (const float*)d_in[6];
    const float* Wv = (const float*)d_in[7];
    const float* gv = (const float*)d_in[8];
    const float* bv = (const float*)d_in[9];
    float* out = (float*)d_out;

    proj_kernel  <<< dim3(16, 8, 24), 256 >>>(x, Wq, Wk, Wv);
    stats_kernel <<< dim3(COUT_, 3, 1), 256 >>>(gq, bq, gk, bk, gv, bv);
    attnE_kernel <<< dim3(16, 16, NBH_), 256 >>>();
    rowsum_kernel<<< NBH_ * P_, 256 >>>();
    out_kernel   <<< dim3(16, 1, NBH_), 256 >>>(out);
}

// round 9
// speedup vs baseline: 2.0291x; 2.0273x over previous
#include <cuda_runtime.h>
#include <cuda_bf16.h>
#include <cstdint>

#define B_    8
#define CIN_  512
#define COUT_ 1024
#define P_    2048
#define H_    8
#define DH_   128
#define NBH_  64
#define EPS_  1e-5f

// ---------------- scratch (device globals; no allocation) ----------------
__device__ float         g_Y[3][(size_t)B_ * COUT_ * P_];   // raw projections
__device__ __nv_bfloat16 g_Wh[3][(size_t)COUT_ * CIN_];
__device__ __nv_bfloat16 g_Wl[3][(size_t)COUT_ * CIN_];
__device__ __nv_bfloat16 g_xth[(size_t)B_ * P_ * CIN_];     // x^T [b][p][c]
__device__ __nv_bfloat16 g_xtl[(size_t)B_ * P_ * CIN_];
__device__ __nv_bfloat16 g_Qh[(size_t)B_ * COUT_ * P_];     // BN+lrelu Q [o][p]
__device__ __nv_bfloat16 g_Ql[(size_t)B_ * COUT_ * P_];
__device__ __nv_bfloat16 g_Kth[(size_t)B_ * P_ * COUT_];    // BN+lrelu K^T [p][o]
__device__ __nv_bfloat16 g_Ktl[(size_t)B_ * P_ * COUT_];
__device__ __nv_bfloat16 g_Vth[(size_t)B_ * P_ * COUT_];
__device__ __nv_bfloat16 g_Vtl[(size_t)B_ * P_ * COUT_];
__device__ __nv_bfloat16 g_Eh[(size_t)NBH_ * P_ * P_];      // exp(logits) hi
__device__ __nv_bfloat16 g_El[(size_t)NBH_ * P_ * P_];      // exp(logits) lo
__device__ float         g_psum[(size_t)NBH_ * P_ * 16];    // partial row sums
__device__ float         g_a[3][COUT_];
__device__ float         g_bsh[3][COUT_];
__device__ float         g_rsinv[NBH_ * P_];

// ---------------- helpers ----------------
__device__ __forceinline__ float lrelu(float v) { return fmaxf(v, 0.1f * v); }

__device__ __forceinline__ uint32_t s2u(const void* p) {
    uint32_t a;
    asm("{ .reg .u64 t; cvta.to.shared.u64 t, %1; cvt.u32.u64 %0, t; }" : "=r"(a) : "l"(p));
    return a;
}
__device__ __forceinline__ void sp2(float v, __nv_bfloat16& h, __nv_bfloat16& l) {
    h = __float2bfloat16(v);
    l = __float2bfloat16(v - __bfloat162float(h));
}
__device__ __forceinline__ uint32_t pack2(__nv_bfloat16 a, __nv_bfloat16 b) {
    uint16_t ua = *(uint16_t*)&a, ub = *(uint16_t*)&b;
    return (uint32_t)ua | ((uint32_t)ub << 16);
}

// ---------------- HMMA building blocks (base-target ISA, sm_80+) --------
#define LDSM4(r, a)                                                          \
    asm volatile("ldmatrix.sync.aligned.m8n8.x4.shared.b16 {%0,%1,%2,%3}, [%4];" \
        : "=r"((r)[0]), "=r"((r)[1]), "=r"((r)[2]), "=r"((r)[3]) : "r"(a))

#define MMAB(c, a, b0, b1)                                                   \
    asm volatile("mma.sync.aligned.m16n8k16.row.col.f32.bf16.bf16.f32 "      \
        "{%0,%1,%2,%3},{%4,%5,%6,%7},{%8,%9},{%0,%1,%2,%3};"                 \
        : "+f"((c)[0]), "+f"((c)[1]), "+f"((c)[2]), "+f"((c)[3])             \
        : "r"((a)[0]), "r"((a)[1]), "r"((a)[2]), "r"((a)[3]),                \
          "r"(b0), "r"(b1))

__device__ __forceinline__ void cpa16(uint32_t dst, const void* src) {
    asm volatile("cp.async.cg.shared.global [%0], [%1], 16;" :: "r"(dst), "l"(src));
}
#define CP_COMMIT() asm volatile("cp.async.commit_group;" ::: "memory")
#define CP_WAIT0()  asm volatile("cp.async.wait_group 0;" ::: "memory")

// Stage tile: 128 rows x 128B. hi occupies 16B-chunks 0-3, lo chunks 4-7,
// chunk position swizzled:  pos = chunk ^ (row & 7)   -> LDSM conflict-free.
// Loads a 128 x 32-bf16 hi/lo pair (k-chunk) via cp.async. 256 threads.
__device__ __forceinline__ void ldstage(uint32_t sdst,
                                        const __nv_bfloat16* hi,
                                        const __nv_bfloat16* lo,
                                        size_t ld, int t) {
#pragma unroll
    for (int i = 0; i < 2; i++) {
        const int id  = t + i * 256;         // 0..511
        const int row = id >> 2, ch = id & 3;
        const uint32_t base = sdst + row * 128;
        cpa16(base + ((ch ^ (row & 7)) << 4),       hi + (size_t)row * ld + ch * 8);
        cpa16(base + (((ch + 4) ^ (row & 7)) << 4), lo + (size_t)row * ld + ch * 8);
    }
}

// One BK=32 stage of 3-term (hi/lo split) HMMA into acc[4][4][4].
// Warp tile 64x32: wrow in {0,1}, wcol in {0..3}.
__device__ __forceinline__ void stage_compute(uint32_t sA, uint32_t sB,
                                              int lane, int wrow, int wcol,
                                              float acc[4][4][4]) {
    const int rA = wrow * 64 + (lane & 15);
    const int rB = wcol * 32 + (lane & 15);
    const int hc = lane >> 4;                 // 0/1: k-halves of ldmatrix.x4
#pragma unroll
    for (int ks = 0; ks < 2; ks++) {
        uint32_t Ah[4][4], Al[4][4], Bh[2][4], Bl[2][4];
        const int ch = ks * 2 + hc;
#pragma unroll
        for (int mi = 0; mi < 4; mi++) {
            const int row = rA + mi * 16;
            const uint32_t base = sA + row * 128;
            LDSM4(Ah[mi], base + ((ch ^ (row & 7)) << 4));
            LDSM4(Al[mi], base + (((ch + 4) ^ (row & 7)) << 4));
        }
#pragma unroll
        for (int np = 0; np < 2; np++) {
            const int row = rB + np * 16;
            const uint32_t base = sB + row * 128;
            LDSM4(Bh[np], base + ((ch ^ (row & 7)) << 4));
            LDSM4(Bl[np], base + (((ch + 4) ^ (row & 7)) << 4));
        }
#pragma unroll
        for (int mi = 0; mi < 4; mi++)
#pragma unroll
            for (int n = 0; n < 4; n++) {
                const int np = n >> 1, sel = n & 1;
                MMAB(acc[mi][n], Ah[mi], Bh[np][sel], Bh[np][2 + sel]);
                MMAB(acc[mi][n], Ah[mi], Bl[np][sel], Bl[np][2 + sel]);
                MMAB(acc[mi][n], Al[mi], Bh[np][sel], Bh[np][2 + sel]);
            }
    }
}

#define SMSZ 65536   // 2 stages x (A 16KB + B 16KB)

// Double-buffered mainloop over NC k-chunks of 32.
#define MAINLOOP(AH, AL, ALD, BH, BL, BLD, NC)                               \
    do {                                                                     \
        ldstage(sb,         (AH), (AL), (ALD), t);                           \
        ldstage(sb + 16384, (BH), (BL), (BLD), t);                           \
        CP_COMMIT();                                                         \
        for (int c = 0; c < (NC); c++) {                                     \
            CP_WAIT0();                                                      \
            __syncthreads();                                                 \
            const int buf = c & 1;                                           \
            if (c + 1 < (NC)) {                                              \
                const uint32_t nb = sb + (buf ^ 1) * 32768;                  \
                ldstage(nb,         (AH) + (c + 1) * 32, (AL) + (c + 1) * 32, (ALD), t); \
                ldstage(nb + 16384, (BH) + (c + 1) * 32, (BL) + (c + 1) * 32, (BLD), t); \
                CP_COMMIT();                                                 \
            }                                                                \
            stage_compute(sb + buf * 32768, sb + buf * 32768 + 16384,        \
                          lane, wrow, wcol, acc);                            \
        }                                                                    \
    } while (0)

// ====================================================================
// split W -> bf16 hi/lo
// ====================================================================
__global__ __launch_bounds__(256) void split_w(
    const float* __restrict__ Wq, const float* __restrict__ Wk,
    const float* __restrict__ Wv)
{
    const int proj = blockIdx.y;
    const float* W = (proj == 0) ? Wq : ((proj == 1) ? Wk : Wv);
    size_t i = ((size_t)blockIdx.x * 256 + threadIdx.x) * 4;
    float4 v = *(const float4*)(W + i);
    __nv_bfloat16 h0,h1,h2,h3,l0,l1,l2,l3;
    sp2(v.x,h0,l0); sp2(v.y,h1,l1); sp2(v.z,h2,l2); sp2(v.w,h3,l3);
    *(uint2*)&g_Wh[proj][i] = make_uint2(pack2(h0,h1), pack2(h2,h3));
    *(uint2*)&g_Wl[proj][i] = make_uint2(pack2(l0,l1), pack2(l2,l3));
}

// ====================================================================
// transpose + split x: [b][c][p] -> [b][p][c] hi/lo
// ====================================================================
__global__ void transpose_x(const float* __restrict__ x)
{
    __shared__ float tile[32][33];
    const int b = blockIdx.z, c0 = blockIdx.y * 32, p0 = blockIdx.x * 32;
    const int tx = threadIdx.x, ty = threadIdx.y;
    const float* X = x + ((size_t)b * CIN_ + c0) * P_ + p0;
#pragma unroll
    for (int i = 0; i < 4; i++)
        tile[ty + i * 8][tx] = X[(size_t)(ty + i * 8) * P_ + tx];
    __syncthreads();
#pragma unroll
    for (int i = 0; i < 4; i++) {
        float v = tile[tx][ty + i * 8];
        __nv_bfloat16 h, l; sp2(v, h, l);
        size_t o = ((size_t)b * P_ + p0 + ty + i * 8) * CIN_ + c0 + tx;
        g_xth[o] = h; g_xtl[o] = l;
    }
}

// ====================================================================
// proj HMMA: Y[proj][b][o][p] = W x.  grid (16 p, 8 o, 24=proj*8+b)
// ====================================================================
__global__ __launch_bounds__(256, 1) void proj_hmma()
{
    extern __shared__ __align__(128) char sm[];
    const int t = threadIdx.x, lane = t & 31, wid = t >> 5;
    const int wrow = wid >> 2, wcol = wid & 3;
    const int proj = blockIdx.z >> 3, b = blockIdx.z & 7;
    const int m0 = blockIdx.y * 128, n0 = blockIdx.x * 128;
    const uint32_t sb = s2u(sm);

    const __nv_bfloat16* Ah = g_Wh[proj] + (size_t)m0 * CIN_;
    const __nv_bfloat16* Al = g_Wl[proj] + (size_t)m0 * CIN_;
    const __nv_bfloat16* Bh = g_xth + ((size_t)b * P_ + n0) * CIN_;
    const __nv_bfloat16* Bl = g_xtl + ((size_t)b * P_ + n0) * CIN_;

    float acc[4][4][4];
#pragma unroll
    for (int i = 0; i < 4; i++)
#pragma unroll
        for (int j = 0; j < 4; j++)
#pragma unroll
            for (int k = 0; k < 4; k++) acc[i][j][k] = 0.0f;

    MAINLOOP(Ah, Al, CIN_, Bh, Bl, CIN_, CIN_ / 32);

    float* Y = g_Y[proj] + (size_t)b * COUT_ * P_;
    const int rbase = m0 + wrow * 64 + (lane >> 2);
    const int cbase = n0 + wcol * 32 + (lane & 3) * 2;
#pragma unroll
    for (int mi = 0; mi < 4; mi++)
#pragma unroll
        for (int n = 0; n < 4; n++) {
            const int r = rbase + mi * 16, cc = cbase + n * 8;
            *(float2*)&Y[(size_t)r * P_ + cc] =
                make_float2(acc[mi][n][0], acc[mi][n][1]);
            *(float2*)&Y[(size_t)(r + 8) * P_ + cc] =
                make_float2(acc[mi][n][2], acc[mi][n][3]);
        }
}

// ====================================================================
// BN stats (deterministic)
// ====================================================================
__global__ __launch_bounds__(256) void stats_kernel(
    const float* __restrict__ gq, const float* __restrict__ bq,
    const float* __restrict__ gk, const float* __restrict__ bk,
    const float* __restrict__ gv, const float* __restrict__ bv)
{
    const int proj = blockIdx.y, ch = blockIdx.x, t = threadIdx.x;
    const float* Ych = g_Y[proj] + (size_t)ch * P_;
    float s = 0.0f, q = 0.0f;
    for (int b = 0; b < B_; b++) {
        const float* row = Ych + (size_t)b * COUT_ * P_;
        for (int p = t * 4; p < P_; p += 1024) {
            float4 v = *(const float4*)&row[p];
            s += v.x + v.y + v.z + v.w;
            q = fmaf(v.x, v.x, q); q = fmaf(v.y, v.y, q);
            q = fmaf(v.z, v.z, q); q = fmaf(v.w, v.w, q);
        }
    }
    __shared__ float rs[256], rq[256];
    rs[t] = s; rq[t] = q;
    __syncthreads();
    for (int st = 128; st > 0; st >>= 1) {
        if (t < st) { rs[t] += rs[t + st]; rq[t] += rq[t + st]; }
        __syncthreads();
    }
    if (t == 0) {
        const float n = (float)(B_ * P_);
        const float mean = rs[0] / n;
        const float var  = rq[0] / n - mean * mean;
        const float* g  = (proj == 0) ? gq : ((proj == 1) ? gk : gv);
        const float* be = (proj == 0) ? bq : ((proj == 1) ? bk : bv);
        const float a = g[ch] * rsqrtf(var + EPS_);
        g_a[proj][ch]   = a;
        g_bsh[proj][ch] = be[ch] - mean * a;
    }
}

// ====================================================================
// finalize Q: BN+lrelu, split hi/lo, keep [o][p]
// ====================================================================
__global__ __launch_bounds__(256) void fin_q()
{
    const int b = blockIdx.z, o = blockIdx.y;
    const float a = g_a[0][o], bs = g_bsh[0][o];
    const size_t off = ((size_t)b * COUT_ + o) * P_ + blockIdx.x * 1024 + threadIdx.x * 4;
    float4 v = *(const float4*)&g_Y[0][off];
    v.x = lrelu(fmaf(a, v.x, bs)); v.y = lrelu(fmaf(a, v.y, bs));
    v.z = lrelu(fmaf(a, v.z, bs)); v.w = lrelu(fmaf(a, v.w, bs));
    __nv_bfloat16 h0,h1,h2,h3,l0,l1,l2,l3;
    sp2(v.x,h0,l0); sp2(v.y,h1,l1); sp2(v.z,h2,l2); sp2(v.w,h3,l3);
    *(uint2*)&g_Qh[off] = make_uint2(pack2(h0,h1), pack2(h2,h3));
    *(uint2*)&g_Ql[off] = make_uint2(pack2(l0,l1), pack2(l2,l3));
}

// ====================================================================
// finalize K/V: BN+lrelu + transpose to [b][p][o], split hi/lo
// ====================================================================
__global__ void fin_kv()
{
    __shared__ float tile[32][33];
    const int z = blockIdx.z, pv = z >> 3, b = z & 7, proj = 1 + pv;
    const int o0 = blockIdx.y * 32, p0 = blockIdx.x * 32;
    const int tx = threadIdx.x, ty = threadIdx.y;
    const float* Y = g_Y[proj] + ((size_t)b * COUT_ + o0) * P_ + p0;
#pragma unroll
    for (int i = 0; i < 4; i++) {
        const int oo = ty + i * 8;
        const float a = g_a[proj][o0 + oo], bs = g_bsh[proj][o0 + oo];
        tile[oo][tx] = lrelu(fmaf(a, Y[(size_t)oo * P_ + tx], bs));
    }
    __syncthreads();
    __nv_bfloat16* Th = pv ? g_Vth : g_Kth;
    __nv_bfloat16* Tl = pv ? g_Vtl : g_Ktl;
#pragma unroll
    for (int i = 0; i < 4; i++) {
        float v = tile[tx][ty + i * 8];
        __nv_bfloat16 h, l; sp2(v, h, l);
        size_t o = ((size_t)b * P_ + p0 + ty + i * 8) * COUT_ + o0 + tx;
        Th[o] = h; Tl[o] = l;
    }
}

// ====================================================================
// attn HMMA: logits = K^T V, then exp + E pack + partial row sums.
// grid (16 j, 16 i, 64 bh)
// ====================================================================
__global__ __launch_bounds__(256, 1) void attn_hmma()
{
    extern __shared__ __align__(128) char sm[];
    __shared__ float ps[2][64][4];
    const int t = threadIdx.x, lane = t & 31, wid = t >> 5;
    const int wrow = wid >> 2, wcol = wid & 3;
    const int bh = blockIdx.z, b = bh >> 3, h = bh & 7;
    const int i0 = blockIdx.y * 128, j0 = blockIdx.x * 128;
    const uint32_t sb = s2u(sm);

    const size_t hoff = (size_t)h * DH_;
    const __nv_bfloat16* Ah = g_Kth + ((size_t)b * P_ + i0) * COUT_ + hoff;
    const __nv_bfloat16* Al = g_Ktl + ((size_t)b * P_ + i0) * COUT_ + hoff;
    const __nv_bfloat16* Bh = g_Vth + ((size_t)b * P_ + j0) * COUT_ + hoff;
    const __nv_bfloat16* Bl = g_Vtl + ((size_t)b * P_ + j0) * COUT_ + hoff;

    float acc[4][4][4];
#pragma unroll
    for (int i = 0; i < 4; i++)
#pragma unroll
        for (int j = 0; j < 4; j++)
#pragma unroll
            for (int k = 0; k < 4; k++) acc[i][j][k] = 0.0f;

    MAINLOOP(Ah, Al, COUT_, Bh, Bl, COUT_, DH_ / 32);

    const float scale = 0.08838834764831845f;  // 1/sqrt(128)
    const int lrow = lane >> 2;
    const int ccol = j0 + wcol * 32 + (lane & 3) * 2;
#pragma unroll
    for (int mi = 0; mi < 4; mi++) {
        const int r = i0 + wrow * 64 + mi * 16 + lrow;
        uint32_t* eh0 = (uint32_t*)(g_Eh + ((size_t)bh * P_ + r) * P_);
        uint32_t* el0 = (uint32_t*)(g_El + ((size_t)bh * P_ + r) * P_);
        uint32_t* eh1 = (uint32_t*)(g_Eh + ((size_t)bh * P_ + r + 8) * P_);
        uint32_t* el1 = (uint32_t*)(g_El + ((size_t)bh * P_ + r + 8) * P_);
        float sa = 0.0f, sb2 = 0.0f;
#pragma unroll
        for (int n = 0; n < 4; n++) {
            const int cw = (ccol + n * 8) >> 1;
            float e0 = __expf(acc[mi][n][0] * scale);
            float e1 = __expf(acc[mi][n][1] * scale);
            float e2 = __expf(acc[mi][n][2] * scale);
            float e3 = __expf(acc[mi][n][3] * scale);
            sa  += e0 + e1;
            sb2 += e2 + e3;
            __nv_bfloat16 h0, l0, h1, l1;
            sp2(e0, h0, l0); sp2(e1, h1, l1);
            eh0[cw] = pack2(h0, h1);  el0[cw] = pack2(l0, l1);
            sp2(e2, h0, l0); sp2(e3, h1, l1);
            eh1[cw] = pack2(h0, h1);  el1[cw] = pack2(l0, l1);
        }
        sa  += __shfl_xor_sync(0xFFFFFFFFu, sa, 1);
        sa  += __shfl_xor_sync(0xFFFFFFFFu, sa, 2);
        sb2 += __shfl_xor_sync(0xFFFFFFFFu, sb2, 1);
        sb2 += __shfl_xor_sync(0xFFFFFFFFu, sb2, 2);
        if ((lane & 3) == 0) {
            ps[wrow][mi * 16 + lrow][wcol]     = sa;
            ps[wrow][mi * 16 + lrow + 8][wcol] = sb2;
        }
    }
    __syncthreads();
    if (t < 128) {
        const int wr = t >> 6, rr = t & 63;
        float s = ps[wr][rr][0] + ps[wr][rr][1] + ps[wr][rr][2] + ps[wr][rr][3];
        g_psum[((size_t)bh * P_ + i0 + wr * 64 + rr) * 16 + blockIdx.x] = s;
    }
}

// ====================================================================
// reduce partial sums -> 1/rowsum
// ====================================================================
__global__ __launch_bounds__(256) void red_psum()
{
    const size_t r = (size_t)blockIdx.x * 256 + threadIdx.x;
    float s = 0.0f;
#pragma unroll
    for (int j = 0; j < 16; j++) s += g_psum[r * 16 + j];
    g_rsinv[r] = 1.0f / s;
}

// ====================================================================
// out HMMA: out[c][i] = rsinv[i] * sum_j Q[c][j] E[i][j]
// grid (16 i-tiles, 1, 64 bh)
// ====================================================================
__global__ __launch_bounds__(256, 1) void out_hmma(float* __restrict__ out)
{
    extern __shared__ __align__(128) char sm[];
    const int t = threadIdx.x, lane = t & 31, wid = t >> 5;
    const int wrow = wid >> 2, wcol = wid & 3;
    const int bh = blockIdx.z, b = bh >> 3, h = bh & 7;
    const int n0 = blockIdx.x * 128;
    const uint32_t sb = s2u(sm);

    const __nv_bfloat16* Ah = g_Qh + ((size_t)b * COUT_ + h * DH_) * P_;
    const __nv_bfloat16* Al = g_Ql + ((size_t)b * COUT_ + h * DH_) * P_;
    const __nv_bfloat16* Bh = g_Eh + ((size_t)bh * P_ + n0) * P_;
    const __nv_bfloat16* Bl = g_El + ((size_t)bh * P_ + n0) * P_;

    float acc[4][4][4];
#pragma unroll
    for (int i = 0; i < 4; i++)
#pragma unroll
        for (int j = 0; j < 4; j++)
#pragma unroll
            for (int k = 0; k < 4; k++) acc[i][j][k] = 0.0f;

    MAINLOOP(Ah, Al, P_, Bh, Bl, P_, P_ / 32);

    const float* inv = g_rsinv + (size_t)bh * P_;
    const int rbase = h * DH_ + wrow * 64 + (lane >> 2);
    const int cbase = n0 + wcol * 32 + (lane & 3) * 2;
#pragma unroll
    for (int mi = 0; mi < 4; mi++)
#pragma unroll
        for (int n = 0; n < 4; n++) {
            const int r = rbase + mi * 16, cc = cbase + n * 8;
            const float i0v = inv[cc], i1v = inv[cc + 1];
            float* o0 = out + ((size_t)b * COUT_ + r) * P_ + cc;
            float* o1 = out + ((size_t)b * COUT_ + r + 8) * P_ + cc;
            *(float2*)o0 = make_float2(acc[mi][n][0] * i0v, acc[mi][n][1] * i1v);
            *(float2*)o1 = make_float2(acc[mi][n][2] * i0v, acc[mi][n][3] * i1v);
        }
}

// ====================================================================
extern "C" void kernel_launch(void* const* d_in, const int* in_sizes, int n_in,
                              void* d_out, int out_size)
{
    const float* x  = (const float*)d_in[0];
    const float* Wq = (const float*)d_in[1];
    const float* gq = (const float*)d_in[2];
    const float* bq = (const float*)d_in[3];
    const float* Wk = (const float*)d_in[4];
    const float* gk = (const float*)d_in[5];
    const float* bk = (const float*)d_in[6];
    const float* Wv = (const float*)d_in[7];
    const float* gv = (const float*)d_in[8];
    const float* bv = (const float*)d_in[9];
    float* out = (float*)d_out;

    cudaFuncSetAttribute(proj_hmma, cudaFuncAttributeMaxDynamicSharedMemorySize, SMSZ);
    cudaFuncSetAttribute(attn_hmma, cudaFuncAttributeMaxDynamicSharedMemorySize, SMSZ);
    cudaFuncSetAttribute(out_hmma,  cudaFuncAttributeMaxDynamicSharedMemorySize, SMSZ);

    split_w     <<< dim3(512, 3), 256 >>>(Wq, Wk, Wv);
    transpose_x <<< dim3(64, 16, 8), dim3(32, 8) >>>(x);
    proj_hmma   <<< dim3(16, 8, 24), 256, SMSZ >>>();
    stats_kernel<<< dim3(COUT_, 3), 256 >>>(gq, bq, gk, bk, gv, bv);
    fin_q       <<< dim3(2, COUT_, B_), 256 >>>();
    fin_kv      <<< dim3(64, 32, 16), dim3(32, 8) >>>();
    attn_hmma   <<< dim3(16, 16, NBH_), 256, SMSZ >>>();
    red_psum    <<< 512, 256 >>>();
    out_hmma    <<< dim3(16, 1, NBH_), 256, SMSZ >>>(out);
}

// round 11
// speedup vs baseline: 2.4209x; 1.1931x over previous
#include <cuda_runtime.h>
#include <cuda_bf16.h>
#include <cstdint>

#define B_    8
#define CIN_  512
#define COUT_ 1024
#define P_    2048
#define H_    8
#define DH_   128
#define NBH_  64
#define EPS_  1e-5f

// ---------------- scratch (device globals; no allocation) ----------------
__device__ float         g_Y[3][(size_t)B_ * COUT_ * P_];   // raw projections
__device__ __nv_bfloat16 g_Wh[3][(size_t)COUT_ * CIN_];
__device__ __nv_bfloat16 g_Wl[3][(size_t)COUT_ * CIN_];
__device__ __nv_bfloat16 g_xth[(size_t)B_ * P_ * CIN_];     // x^T [b][p][c]
__device__ __nv_bfloat16 g_xtl[(size_t)B_ * P_ * CIN_];
__device__ __nv_bfloat16 g_Qh[(size_t)B_ * COUT_ * P_];     // BN+lrelu Q [o][p]
__device__ __nv_bfloat16 g_Ql[(size_t)B_ * COUT_ * P_];
__device__ __nv_bfloat16 g_Kth[(size_t)B_ * P_ * COUT_];    // BN+lrelu K^T [p][o]
__device__ __nv_bfloat16 g_Ktl[(size_t)B_ * P_ * COUT_];
__device__ __nv_bfloat16 g_Vth[(size_t)B_ * P_ * COUT_];
__device__ __nv_bfloat16 g_Vtl[(size_t)B_ * P_ * COUT_];
__device__ __nv_bfloat16 g_Eh[(size_t)NBH_ * P_ * P_];      // exp(logits) hi
__device__ __nv_bfloat16 g_El[(size_t)NBH_ * P_ * P_];      // exp(logits) lo
__device__ float         g_psum[(size_t)NBH_ * P_ * 16];    // partial row sums
__device__ float         g_a[3][COUT_];
__device__ float         g_bsh[3][COUT_];
__device__ float         g_rsinv[NBH_ * P_];

// ---------------- helpers ----------------
__device__ __forceinline__ float lrelu(float v) { return fmaxf(v, 0.1f * v); }

__device__ __forceinline__ uint32_t s2u(const void* p) {
    uint32_t a;
    asm("{ .reg .u64 t; cvta.to.shared.u64 t, %1; cvt.u32.u64 %0, t; }" : "=r"(a) : "l"(p));
    return a;
}
__device__ __forceinline__ void sp2(float v, __nv_bfloat16& h, __nv_bfloat16& l) {
    h = __float2bfloat16(v);
    l = __float2bfloat16(v - __bfloat162float(h));
}
__device__ __forceinline__ uint32_t pack2(__nv_bfloat16 a, __nv_bfloat16 b) {
    uint16_t ua = *(uint16_t*)&a, ub = *(uint16_t*)&b;
    return (uint32_t)ua | ((uint32_t)ub << 16);
}

// ---------------- HMMA building blocks (base-target ISA, sm_80+) --------
#define LDSM4(r, a)                                                          \
    asm volatile("ldmatrix.sync.aligned.m8n8.x4.shared.b16 {%0,%1,%2,%3}, [%4];" \
        : "=r"((r)[0]), "=r"((r)[1]), "=r"((r)[2]), "=r"((r)[3]) : "r"(a))

#define MMAB(c, a, b0, b1)                                                   \
    asm volatile("mma.sync.aligned.m16n8k16.row.col.f32.bf16.bf16.f32 "      \
        "{%0,%1,%2,%3},{%4,%5,%6,%7},{%8,%9},{%0,%1,%2,%3};"                 \
        : "+f"((c)[0]), "+f"((c)[1]), "+f"((c)[2]), "+f"((c)[3])             \
        : "r"((a)[0]), "r"((a)[1]), "r"((a)[2]), "r"((a)[3]),                \
          "r"(b0), "r"(b1))

__device__ __forceinline__ void cpa16(uint32_t dst, const void* src) {
    asm volatile("cp.async.cg.shared.global [%0], [%1], 16;" :: "r"(dst), "l"(src));
}
#define CP_COMMIT() asm volatile("cp.async.commit_group;" ::: "memory")
#define CP_WAIT0()  asm volatile("cp.async.wait_group 0;" ::: "memory")

// Stage tile: 128 rows x 128B. hi occupies 16B-chunks 0-3, lo chunks 4-7,
// chunk position swizzled:  pos = chunk ^ (row & 7)   -> LDSM conflict-free.
// Loads a 128 x 32-bf16 hi/lo pair (k-chunk) via cp.async. 256 threads.
__device__ __forceinline__ void ldstage(uint32_t sdst,
                                        const __nv_bfloat16* hi,
                                        const __nv_bfloat16* lo,
                                        size_t ld, int t) {
#pragma unroll
    for (int i = 0; i < 2; i++) {
        const int id  = t + i * 256;         // 0..511
        const int row = id >> 2, ch = id & 3;
        const uint32_t base = sdst + row * 128;
        cpa16(base + ((ch ^ (row & 7)) << 4),       hi + (size_t)row * ld + ch * 8);
        cpa16(base + (((ch + 4) ^ (row & 7)) << 4), lo + (size_t)row * ld + ch * 8);
    }
}

// One BK=32 stage of 3-term (hi/lo split) HMMA into acc[4][4][4].
// Warp tile 64x32: wrow in {0,1}, wcol in {0..3}.
// Restructured for low register pressure: B frags hoisted per k-slice,
// A frags loaded per-mi right before use (live set ~105 regs incl. acc).
__device__ __forceinline__ void stage_compute(uint32_t sA, uint32_t sB,
                                              int lane, int wrow, int wcol,
                                              float acc[4][4][4]) {
    const int rA = wrow * 64 + (lane & 15);
    const int rB = wcol * 32 + (lane & 15);
    const int hc = lane >> 4;                 // 0/1: k-halves of ldmatrix.x4
#pragma unroll
    for (int ks = 0; ks < 2; ks++) {
        const int ch = ks * 2 + hc;
        uint32_t Bh[2][4], Bl[2][4];
#pragma unroll
        for (int np = 0; np < 2; np++) {
            const int row = rB + np * 16;
            const uint32_t base = sB + row * 128;
            LDSM4(Bh[np], base + ((ch ^ (row & 7)) << 4));
            LDSM4(Bl[np], base + (((ch + 4) ^ (row & 7)) << 4));
        }
#pragma unroll
        for (int mi = 0; mi < 4; mi++) {
            uint32_t Ah[4], Al[4];
            const int row = rA + mi * 16;
            const uint32_t base = sA + row * 128;
            LDSM4(Ah, base + ((ch ^ (row & 7)) << 4));
            LDSM4(Al, base + (((ch + 4) ^ (row & 7)) << 4));
#pragma unroll
            for (int n = 0; n < 4; n++) {
                const int np = n >> 1, sel = n & 1;
                MMAB(acc[mi][n], Ah, Bh[np][sel], Bh[np][2 + sel]);
                MMAB(acc[mi][n], Ah, Bl[np][sel], Bl[np][2 + sel]);
                MMAB(acc[mi][n], Al, Bh[np][sel], Bh[np][2 + sel]);
            }
        }
    }
}

#define SMSZ 65536   // 2 stages x (A 16KB + B 16KB); 2 blocks/SM = 128KB

// Double-buffered mainloop over NC k-chunks of 32.
#define MAINLOOP(AH, AL, ALD, BH, BL, BLD, NC)                               \
    do {                                                                     \
        ldstage(sb,         (AH), (AL), (ALD), t);                           \
        ldstage(sb + 16384, (BH), (BL), (BLD), t);                           \
        CP_COMMIT();                                                         \
        for (int c = 0; c < (NC); c++) {                                     \
            CP_WAIT0();                                                      \
            __syncthreads();                                                 \
            const int buf = c & 1;                                           \
            if (c + 1 < (NC)) {                                              \
                const uint32_t nb = sb + (buf ^ 1) * 32768;                  \
                ldstage(nb,         (AH) + (c + 1) * 32, (AL) + (c + 1) * 32, (ALD), t); \
                ldstage(nb + 16384, (BH) + (c + 1) * 32, (BL) + (c + 1) * 32, (BLD), t); \
                CP_COMMIT();                                                 \
            }                                                                \
            stage_compute(sb + buf * 32768, sb + buf * 32768 + 16384,        \
                          lane, wrow, wcol, acc);                            \
        }                                                                    \
    } while (0)

// ====================================================================
// split W -> bf16 hi/lo
// ====================================================================
__global__ __launch_bounds__(256) void split_w(
    const float* __restrict__ Wq, const float* __restrict__ Wk,
    const float* __restrict__ Wv)
{
    const int proj = blockIdx.y;
    const float* W = (proj == 0) ? Wq : ((proj == 1) ? Wk : Wv);
    size_t i = ((size_t)blockIdx.x * 256 + threadIdx.x) * 4;
    float4 v = *(const float4*)(W + i);
    __nv_bfloat16 h0,h1,h2,h3,l0,l1,l2,l3;
    sp2(v.x,h0,l0); sp2(v.y,h1,l1); sp2(v.z,h2,l2); sp2(v.w,h3,l3);
    *(uint2*)&g_Wh[proj][i] = make_uint2(pack2(h0,h1), pack2(h2,h3));
    *(uint2*)&g_Wl[proj][i] = make_uint2(pack2(l0,l1), pack2(l2,l3));
}

// ====================================================================
// transpose + split x: [b][c][p] -> [b][p][c] hi/lo
// ====================================================================
__global__ void transpose_x(const float* __restrict__ x)
{
    __shared__ float tile[32][33];
    const int b = blockIdx.z, c0 = blockIdx.y * 32, p0 = blockIdx.x * 32;
    const int tx = threadIdx.x, ty = threadIdx.y;
    const float* X = x + ((size_t)b * CIN_ + c0) * P_ + p0;
#pragma unroll
    for (int i = 0; i < 4; i++)
        tile[ty + i * 8][tx] = X[(size_t)(ty + i * 8) * P_ + tx];
    __syncthreads();
#pragma unroll
    for (int i = 0; i < 4; i++) {
        float v = tile[tx][ty + i * 8];
        __nv_bfloat16 h, l; sp2(v, h, l);
        size_t o = ((size_t)b * P_ + p0 + ty + i * 8) * CIN_ + c0 + tx;
        g_xth[o] = h; g_xtl[o] = l;
    }
}

// ====================================================================
// proj HMMA: Y[proj][b][o][p] = W x.  grid (16 p, 8 o, 24=proj*8+b)
// ====================================================================
__global__ __launch_bounds__(256, 2) void proj_hmma()
{
    extern __shared__ __align__(128) char sm[];
    const int t = threadIdx.x, lane = t & 31, wid = t >> 5;
    const int wrow = wid >> 2, wcol = wid & 3;
    const int proj = blockIdx.z >> 3, b = blockIdx.z & 7;
    const int m0 = blockIdx.y * 128, n0 = blockIdx.x * 128;
    const uint32_t sb = s2u(sm);

    const __nv_bfloat16* Ah = g_Wh[proj] + (size_t)m0 * CIN_;
    const __nv_bfloat16* Al = g_Wl[proj] + (size_t)m0 * CIN_;
    const __nv_bfloat16* Bh = g_xth + ((size_t)b * P_ + n0) * CIN_;
    const __nv_bfloat16* Bl = g_xtl + ((size_t)b * P_ + n0) * CIN_;

    float acc[4][4][4];
#pragma unroll
    for (int i = 0; i < 4; i++)
#pragma unroll
        for (int j = 0; j < 4; j++)
#pragma unroll
            for (int k = 0; k < 4; k++) acc[i][j][k] = 0.0f;

    MAINLOOP(Ah, Al, CIN_, Bh, Bl, CIN_, CIN_ / 32);

    float* Y = g_Y[proj] + (size_t)b * COUT_ * P_;
    const int rbase = m0 + wrow * 64 + (lane >> 2);
    const int cbase = n0 + wcol * 32 + (lane & 3) * 2;
#pragma unroll
    for (int mi = 0; mi < 4; mi++)
#pragma unroll
        for (int n = 0; n < 4; n++) {
            const int r = rbase + mi * 16, cc = cbase + n * 8;
            *(float2*)&Y[(size_t)r * P_ + cc] =
                make_float2(acc[mi][n][0], acc[mi][n][1]);
            *(float2*)&Y[(size_t)(r + 8) * P_ + cc] =
                make_float2(acc[mi][n][2], acc[mi][n][3]);
        }
}

// ====================================================================
// BN stats (deterministic)
// ====================================================================
__global__ __launch_bounds__(256) void stats_kernel(
    const float* __restrict__ gq, const float* __restrict__ bq,
    const float* __restrict__ gk, const float* __restrict__ bk,
    const float* __restrict__ gv, const float* __restrict__ bv)
{
    const int proj = blockIdx.y, ch = blockIdx.x, t = threadIdx.x;
    const float* Ych = g_Y[proj] + (size_t)ch * P_;
    float s = 0.0f, q = 0.0f;
    for (int b = 0; b < B_; b++) {
        const float* row = Ych + (size_t)b * COUT_ * P_;
        for (int p = t * 4; p < P_; p += 1024) {
            float4 v = *(const float4*)&row[p];
            s += v.x + v.y + v.z + v.w;
            q = fmaf(v.x, v.x, q); q = fmaf(v.y, v.y, q);
            q = fmaf(v.z, v.z, q); q = fmaf(v.w, v.w, q);
        }
    }
    __shared__ float rs[256], rq[256];
    rs[t] = s; rq[t] = q;
    __syncthreads();
    for (int st = 128; st > 0; st >>= 1) {
        if (t < st) { rs[t] += rs[t + st]; rq[t] += rq[t + st]; }
        __syncthreads();
    }
    if (t == 0) {
        const float n = (float)(B_ * P_);
        const float mean = rs[0] / n;
        const float var  = rq[0] / n - mean * mean;
        const float* g  = (proj == 0) ? gq : ((proj == 1) ? gk : gv);
        const float* be = (proj == 0) ? bq : ((proj == 1) ? bk : bv);
        const float a = g[ch] * rsqrtf(var + EPS_);
        g_a[proj][ch]   = a;
        g_bsh[proj][ch] = be[ch] - mean * a;
    }
}

// ====================================================================
// finalize Q: BN+lrelu, split hi/lo, keep [o][p]
// ====================================================================
__global__ __launch_bounds__(256) void fin_q()
{
    const int b = blockIdx.z, o = blockIdx.y;
    const float a = g_a[0][o], bs = g_bsh[0][o];
    const size_t off = ((size_t)b * COUT_ + o) * P_ + blockIdx.x * 1024 + threadIdx.x * 4;
    float4 v = *(const float4*)&g_Y[0][off];
    v.x = lrelu(fmaf(a, v.x, bs)); v.y = lrelu(fmaf(a, v.y, bs));
    v.z = lrelu(fmaf(a, v.z, bs)); v.w = lrelu(fmaf(a, v.w, bs));
    __nv_bfloat16 h0,h1,h2,h3,l0,l1,l2,l3;
    sp2(v.x,h0,l0); sp2(v.y,h1,l1); sp2(v.z,h2,l2); sp2(v.w,h3,l3);
    *(uint2*)&g_Qh[off] = make_uint2(pack2(h0,h1), pack2(h2,h3));
    *(uint2*)&g_Ql[off] = make_uint2(pack2(l0,l1), pack2(l2,l3));
}

// ====================================================================
// finalize K/V: BN+lrelu + transpose to [b][p][o], split hi/lo
// ====================================================================
__global__ void fin_kv()
{
    __shared__ float tile[32][33];
    const int z = blockIdx.z, pv = z >> 3, b = z & 7, proj = 1 + pv;
    const int o0 = blockIdx.y * 32, p0 = blockIdx.x * 32;
    const int tx = threadIdx.x, ty = threadIdx.y;
    const float* Y = g_Y[proj] + ((size_t)b * COUT_ + o0) * P_ + p0;
#pragma unroll
    for (int i = 0; i < 4; i++) {
        const int oo = ty + i * 8;
        const float a = g_a[proj][o0 + oo], bs = g_bsh[proj][o0 + oo];
        tile[oo][tx] = lrelu(fmaf(a, Y[(size_t)oo * P_ + tx], bs));
    }
    __syncthreads();
    __nv_bfloat16* Th = pv ? g_Vth : g_Kth;
    __nv_bfloat16* Tl = pv ? g_Vtl : g_Ktl;
#pragma unroll
    for (int i = 0; i < 4; i++) {
        float v = tile[tx][ty + i * 8];
        __nv_bfloat16 h, l; sp2(v, h, l);
        size_t o = ((size_t)b * P_ + p0 + ty + i * 8) * COUT_ + o0 + tx;
        Th[o] = h; Tl[o] = l;
    }
}

// ====================================================================
// attn HMMA: logits = K^T V, then exp + E pack + partial row sums.
// grid (16 j, 16 i, 64 bh)
// ====================================================================
__global__ __launch_bounds__(256, 2) void attn_hmma()
{
    extern __shared__ __align__(128) char sm[];
    __shared__ float ps[2][64][4];
    const int t = threadIdx.x, lane = t & 31, wid = t >> 5;
    const int wrow = wid >> 2, wcol = wid & 3;
    const int bh = blockIdx.z, b = bh >> 3, h = bh & 7;
    const int i0 = blockIdx.y * 128, j0 = blockIdx.x * 128;
    const uint32_t sb = s2u(sm);

    const size_t hoff = (size_t)h * DH_;
    const __nv_bfloat16* Ah = g_Kth + ((size_t)b * P_ + i0) * COUT_ + hoff;
    const __nv_bfloat16* Al = g_Ktl + ((size_t)b * P_ + i0) * COUT_ + hoff;
    const __nv_bfloat16* Bh = g_Vth + ((size_t)b * P_ + j0) * COUT_ + hoff;
    const __nv_bfloat16* Bl = g_Vtl + ((size_t)b * P_ + j0) * COUT_ + hoff;

    float acc[4][4][4];
#pragma unroll
    for (int i = 0; i < 4; i++)
#pragma unroll
        for (int j = 0; j < 4; j++)
#pragma unroll
            for (int k = 0; k < 4; k++) acc[i][j][k] = 0.0f;

    MAINLOOP(Ah, Al, COUT_, Bh, Bl, COUT_, DH_ / 32);

    const float scale = 0.08838834764831845f;  // 1/sqrt(128)
    const int lrow = lane >> 2;
    const int ccol = j0 + wcol * 32 + (lane & 3) * 2;
#pragma unroll
    for (int mi = 0; mi < 4; mi++) {
        const int r = i0 + wrow * 64 + mi * 16 + lrow;
        uint32_t* eh0 = (uint32_t*)(g_Eh + ((size_t)bh * P_ + r) * P_);
        uint32_t* el0 = (uint32_t*)(g_El + ((size_t)bh * P_ + r) * P_);
        uint32_t* eh1 = (uint32_t*)(g_Eh + ((size_t)bh * P_ + r + 8) * P_);
        uint32_t* el1 = (uint32_t*)(g_El + ((size_t)bh * P_ + r + 8) * P_);
        float sa = 0.0f, sb2 = 0.0f;
#pragma unroll
        for (int n = 0; n < 4; n++) {
            const int cw = (ccol + n * 8) >> 1;
            float e0 = __expf(acc[mi][n][0] * scale);
            float e1 = __expf(acc[mi][n][1] * scale);
            float e2 = __expf(acc[mi][n][2] * scale);
            float e3 = __expf(acc[mi][n][3] * scale);
            sa  += e0 + e1;
            sb2 += e2 + e3;
            __nv_bfloat16 h0, l0, h1, l1;
            sp2(e0, h0, l0); sp2(e1, h1, l1);
            eh0[cw] = pack2(h0, h1);  el0[cw] = pack2(l0, l1);
            sp2(e2, h0, l0); sp2(e3, h1, l1);
            eh1[cw] = pack2(h0, h1);  el1[cw] = pack2(l0, l1);
        }
        sa  += __shfl_xor_sync(0xFFFFFFFFu, sa, 1);
        sa  += __shfl_xor_sync(0xFFFFFFFFu, sa, 2);
        sb2 += __shfl_xor_sync(0xFFFFFFFFu, sb2, 1);
        sb2 += __shfl_xor_sync(0xFFFFFFFFu, sb2, 2);
        if ((lane & 3) == 0) {
            ps[wrow][mi * 16 + lrow][wcol]     = sa;
            ps[wrow][mi * 16 + lrow + 8][wcol] = sb2;
        }
    }
    __syncthreads();
    if (t < 128) {
        const int wr = t >> 6, rr = t & 63;
        float s = ps[wr][rr][0] + ps[wr][rr][1] + ps[wr][rr][2] + ps[wr][rr][3];
        g_psum[((size_t)bh * P_ + i0 + wr * 64 + rr) * 16 + blockIdx.x] = s;
    }
}

// ====================================================================
// reduce partial sums -> 1/rowsum
// ====================================================================
__global__ __launch_bounds__(256) void red_psum()
{
    const size_t r = (size_t)blockIdx.x * 256 + threadIdx.x;
    const float4* p = (const float4*)(g_psum + r * 16);
    float4 a = p[0], b = p[1], c = p[2], d = p[3];
    float s = a.x + a.y + a.z + a.w + b.x + b.y + b.z + b.w
            + c.x + c.y + c.z + c.w + d.x + d.y + d.z + d.w;
    g_rsinv[r] = 1.0f / s;
}

// ====================================================================
// out HMMA: out[c][i] = rsinv[i] * sum_j Q[c][j] E[i][j]
// grid (16 i-tiles, 1, 64 bh)
// ====================================================================
__global__ __launch_bounds__(256, 2) void out_hmma(float* __restrict__ out)
{
    extern __shared__ __align__(128) char sm[];
    const int t = threadIdx.x, lane = t & 31, wid = t >> 5;
    const int wrow = wid >> 2, wcol = wid & 3;
    const int bh = blockIdx.z, b = bh >> 3, h = bh & 7;
    const int n0 = blockIdx.x * 128;
    const uint32_t sb = s2u(sm);

    const __nv_bfloat16* Ah = g_Qh + ((size_t)b * COUT_ + h * DH_) * P_;
    const __nv_bfloat16* Al = g_Ql + ((size_t)b * COUT_ + h * DH_) * P_;
    const __nv_bfloat16* Bh = g_Eh + ((size_t)bh * P_ + n0) * P_;
    const __nv_bfloat16* Bl = g_El + ((size_t)bh * P_ + n0) * P_;

    float acc[4][4][4];
#pragma unroll
    for (int i = 0; i < 4; i++)
#pragma unroll
        for (int j = 0; j < 4; j++)
#pragma unroll
            for (int k = 0; k < 4; k++) acc[i][j][k] = 0.0f;

    MAINLOOP(Ah, Al, P_, Bh, Bl, P_, P_ / 32);

    const float* inv = g_rsinv + (size_t)bh * P_;
    const int rbase = h * DH_ + wrow * 64 + (lane >> 2);
    const int cbase = n0 + wcol * 32 + (lane & 3) * 2;
#pragma unroll
    for (int mi = 0; mi < 4; mi++)
#pragma unroll
        for (int n = 0; n < 4; n++) {
            const int r = rbase + mi * 16, cc = cbase + n * 8;
            const float i0v = inv[cc], i1v = inv[cc + 1];
            float* o0 = out + ((size_t)b * COUT_ + r) * P_ + cc;
            float* o1 = out + ((size_t)b * COUT_ + r + 8) * P_ + cc;
            *(float2*)o0 = make_float2(acc[mi][n][0] * i0v, acc[mi][n][1] * i1v);
            *(float2*)o1 = make_float2(acc[mi][n][2] * i0v, acc[mi][n][3] * i1v);
        }
}

// ====================================================================
extern "C" void kernel_launch(void* const* d_in, const int* in_sizes, int n_in,
                              void* d_out, int out_size)
{
    const float* x  = (const float*)d_in[0];
    const float* Wq = (const float*)d_in[1];
    const float* gq = (const float*)d_in[2];
    const float* bq = (const float*)d_in[3];
    const float* Wk = (const float*)d_in[4];
    const float* gk = (const float*)d_in[5];
    const float* bk = (const float*)d_in[6];
    const float* Wv = (const float*)d_in[7];
    const float* gv = (const float*)d_in[8];
    const float* bv = (const float*)d_in[9];
    float* out = (float*)d_out;

    cudaFuncSetAttribute(proj_hmma, cudaFuncAttributeMaxDynamicSharedMemorySize, SMSZ);
    cudaFuncSetAttribute(attn_hmma, cudaFuncAttributeMaxDynamicSharedMemorySize, SMSZ);
    cudaFuncSetAttribute(out_hmma,  cudaFuncAttributeMaxDynamicSharedMemorySize, SMSZ);

    split_w     <<< dim3(512, 3), 256 >>>(Wq, Wk, Wv);
    transpose_x <<< dim3(64, 16, 8), dim3(32, 8) >>>(x);
    proj_hmma   <<< dim3(16, 8, 24), 256, SMSZ >>>();
    stats_kernel<<< dim3(COUT_, 3), 256 >>>(gq, bq, gk, bk, gv, bv);
    fin_q       <<< dim3(2, COUT_, B_), 256 >>>();
    fin_kv      <<< dim3(64, 32, 16), dim3(32, 8) >>>();
    attn_hmma   <<< dim3(16, 16, NBH_), 256, SMSZ >>>();
    red_psum    <<< 512, 256 >>>();
    out_hmma    <<< dim3(16, 1, NBH_), 256, SMSZ >>>(out);
}

// round 14
// speedup vs baseline: 3.2684x; 1.3501x over previous
#include <cuda_runtime.h>
#include <cuda_bf16.h>
#include <cuda_fp16.h>
#include <cstdint>

#define B_    8
#define CIN_  512
#define COUT_ 1024
#define P_    2048
#define H_    8
#define DH_   128
#define NBH_  64
#define EPS_  1e-5f

// ---------------- scratch (device globals; no allocation) ----------------
__device__ float         g_Y[3][(size_t)B_ * COUT_ * P_];   // raw projections
__device__ __nv_bfloat16 g_Wh[3][(size_t)COUT_ * CIN_];
__device__ __nv_bfloat16 g_Wl[3][(size_t)COUT_ * CIN_];
__device__ __nv_bfloat16 g_xth[(size_t)B_ * P_ * CIN_];     // x^T [b][p][c]
__device__ __nv_bfloat16 g_xtl[(size_t)B_ * P_ * CIN_];
__device__ __half        g_Qh[(size_t)B_ * COUT_ * P_];     // BN+lrelu Q [o][p] fp16 hi
__device__ __half        g_Ql[(size_t)B_ * COUT_ * P_];     // fp16 lo
__device__ __half        g_Kth[(size_t)B_ * P_ * COUT_];    // BN+lrelu K^T [p][o] fp16 (hi only)
__device__ __half        g_Vth[(size_t)B_ * P_ * COUT_];    // V^T fp16 hi
__device__ __half        g_Vtl[(size_t)B_ * P_ * COUT_];    // V^T fp16 lo
__device__ __half        g_E[(size_t)NBH_ * P_ * P_];       // exp(logits) fp16 (single)
__device__ float         g_psum[(size_t)NBH_ * P_ * 16];    // partial row sums
__device__ float         g_a[3][COUT_];
__device__ float         g_bsh[3][COUT_];
__device__ float         g_rsinv[NBH_ * P_];

// ---------------- helpers ----------------
__device__ __forceinline__ float lrelu(float v) { return fmaxf(v, 0.1f * v); }

__device__ __forceinline__ uint32_t s2u(const void* p) {
    uint32_t a;
    asm("{ .reg .u64 t; cvta.to.shared.u64 t, %1; cvt.u32.u64 %0, t; }" : "=r"(a) : "l"(p));
    return a;
}
__device__ __forceinline__ void sp2(float v, __nv_bfloat16& h, __nv_bfloat16& l) {
    h = __float2bfloat16(v);
    l = __float2bfloat16(v - __bfloat162float(h));
}
__device__ __forceinline__ void sp2h(float v, __half& h, __half& l) {
    h = __float2half_rn(v);
    l = __float2half_rn(v - __half2float(h));
}
__device__ __forceinline__ uint32_t pack2(__nv_bfloat16 a, __nv_bfloat16 b) {
    uint16_t ua = *(uint16_t*)&a, ub = *(uint16_t*)&b;
    return (uint32_t)ua | ((uint32_t)ub << 16);
}
__device__ __forceinline__ uint32_t pack2h(__half a, __half b) {
    uint16_t ua = *(uint16_t*)&a, ub = *(uint16_t*)&b;
    return (uint32_t)ua | ((uint32_t)ub << 16);
}

// ---------------- HMMA building blocks (base-target ISA, sm_80+) --------
#define LDSM4(r, a)                                                          \
    asm volatile("ldmatrix.sync.aligned.m8n8.x4.shared.b16 {%0,%1,%2,%3}, [%4];" \
        : "=r"((r)[0]), "=r"((r)[1]), "=r"((r)[2]), "=r"((r)[3]) : "r"(a))

#define MMAB(c, a, b0, b1)                                                   \
    asm volatile("mma.sync.aligned.m16n8k16.row.col.f32.bf16.bf16.f32 "      \
        "{%0,%1,%2,%3},{%4,%5,%6,%7},{%8,%9},{%0,%1,%2,%3};"                 \
        : "+f"((c)[0]), "+f"((c)[1]), "+f"((c)[2]), "+f"((c)[3])             \
        : "r"((a)[0]), "r"((a)[1]), "r"((a)[2]), "r"((a)[3]),                \
          "r"(b0), "r"(b1))

#define MMAH(c, a, b0, b1)                                                   \
    asm volatile("mma.sync.aligned.m16n8k16.row.col.f32.f16.f16.f32 "        \
        "{%0,%1,%2,%3},{%4,%5,%6,%7},{%8,%9},{%0,%1,%2,%3};"                 \
        : "+f"((c)[0]), "+f"((c)[1]), "+f"((c)[2]), "+f"((c)[3])             \
        : "r"((a)[0]), "r"((a)[1]), "r"((a)[2]), "r"((a)[3]),                \
          "r"(b0), "r"(b1))

__device__ __forceinline__ void cpa16(uint32_t dst, const void* src) {
    asm volatile("cp.async.cg.shared.global [%0], [%1], 16;" :: "r"(dst), "l"(src));
}
#define CP_COMMIT() asm volatile("cp.async.commit_group;" ::: "memory")
#define CP_WAIT0()  asm volatile("cp.async.wait_group 0;" ::: "memory")

// Stage tile: 128 rows x 128B. hi occupies 16B-chunks 0-3, lo chunks 4-7,
// chunk position swizzled:  pos = chunk ^ (row & 7)   -> LDSM conflict-free.
// ldstage_p: hi+lo pair (full 16KB tile).  ldstage_s: hi only (chunks 0-3).
template <typename T>
__device__ __forceinline__ void ldstage_p(uint32_t sdst, const T* hi,
                                          const T* lo, size_t ld, int t) {
#pragma unroll
    for (int i = 0; i < 2; i++) {
        const int id  = t + i * 256;         // 0..511
        const int row = id >> 2, ch = id & 3;
        const uint32_t base = sdst + row * 128;
        cpa16(base + ((ch ^ (row & 7)) << 4),       hi + (size_t)row * ld + ch * 8);
        cpa16(base + (((ch + 4) ^ (row & 7)) << 4), lo + (size_t)row * ld + ch * 8);
    }
}
template <typename T>
__device__ __forceinline__ void ldstage_s(uint32_t sdst, const T* hi,
                                          size_t ld, int t) {
#pragma unroll
    for (int i = 0; i < 2; i++) {
        const int id  = t + i * 256;
        const int row = id >> 2, ch = id & 3;
        cpa16(sdst + row * 128 + ((ch ^ (row & 7)) << 4),
              hi + (size_t)row * ld + ch * 8);
    }
}

// ---- bf16 3-term stage (A pair x B pair), used by proj ----
__device__ __forceinline__ void stage_pp3(uint32_t sA, uint32_t sB,
                                          int lane, int wrow, int wcol,
                                          float acc[4][4][4]) {
    const int rA = wrow * 64 + (lane & 15);
    const int rB = wcol * 32 + (lane & 15);
    const int hc = lane >> 4;
#pragma unroll
    for (int ks = 0; ks < 2; ks++) {
        const int ch = ks * 2 + hc;
        uint32_t Bh[2][4], Bl[2][4];
#pragma unroll
        for (int np = 0; np < 2; np++) {
            const int row = rB + np * 16;
            const uint32_t base = sB + row * 128;
            LDSM4(Bh[np], base + ((ch ^ (row & 7)) << 4));
            LDSM4(Bl[np], base + (((ch + 4) ^ (row & 7)) << 4));
        }
#pragma unroll
        for (int mi = 0; mi < 4; mi++) {
            uint32_t Ah[4], Al[4];
            const int row = rA + mi * 16;
            const uint32_t base = sA + row * 128;
            LDSM4(Ah, base + ((ch ^ (row & 7)) << 4));
            LDSM4(Al, base + (((ch + 4) ^ (row & 7)) << 4));
#pragma unroll
            for (int n = 0; n < 4; n++) {
                const int np = n >> 1, sel = n & 1;
                MMAB(acc[mi][n], Ah, Bh[np][sel], Bh[np][2 + sel]);
                MMAB(acc[mi][n], Ah, Bl[np][sel], Bl[np][2 + sel]);
                MMAB(acc[mi][n], Al, Bh[np][sel], Bh[np][2 + sel]);
            }
        }
    }
}

// ---- fp16 2-term stage: A single x B pair (attn: K x V) ----
__device__ __forceinline__ void stage_sp2(uint32_t sA, uint32_t sB,
                                          int lane, int wrow, int wcol,
                                          float acc[4][4][4]) {
    const int rA = wrow * 64 + (lane & 15);
    const int rB = wcol * 32 + (lane & 15);
    const int hc = lane >> 4;
#pragma unroll
    for (int ks = 0; ks < 2; ks++) {
        const int ch = ks * 2 + hc;
        uint32_t Bh[2][4], Bl[2][4];
#pragma unroll
        for (int np = 0; np < 2; np++) {
            const int row = rB + np * 16;
            const uint32_t base = sB + row * 128;
            LDSM4(Bh[np], base + ((ch ^ (row & 7)) << 4));
            LDSM4(Bl[np], base + (((ch + 4) ^ (row & 7)) << 4));
        }
#pragma unroll
        for (int mi = 0; mi < 4; mi++) {
            uint32_t Ah[4];
            const int row = rA + mi * 16;
            LDSM4(Ah, sA + row * 128 + ((ch ^ (row & 7)) << 4));
#pragma unroll
            for (int n = 0; n < 4; n++) {
                const int np = n >> 1, sel = n & 1;
                MMAH(acc[mi][n], Ah, Bh[np][sel], Bh[np][2 + sel]);
                MMAH(acc[mi][n], Ah, Bl[np][sel], Bl[np][2 + sel]);
            }
        }
    }
}

// ---- fp16 2-term stage: A pair x B single (out: Q x E) ----
__device__ __forceinline__ void stage_ps2(uint32_t sA, uint32_t sB,
                                          int lane, int wrow, int wcol,
                                          float acc[4][4][4]) {
    const int rA = wrow * 64 + (lane & 15);
    const int rB = wcol * 32 + (lane & 15);
    const int hc = lane >> 4;
#pragma unroll
    for (int ks = 0; ks < 2; ks++) {
        const int ch = ks * 2 + hc;
        uint32_t Bh[2][4];
#pragma unroll
        for (int np = 0; np < 2; np++) {
            const int row = rB + np * 16;
            LDSM4(Bh[np], sB + row * 128 + ((ch ^ (row & 7)) << 4));
        }
#pragma unroll
        for (int mi = 0; mi < 4; mi++) {
            uint32_t Ah[4], Al[4];
            const int row = rA + mi * 16;
            const uint32_t base = sA + row * 128;
            LDSM4(Ah, base + ((ch ^ (row & 7)) << 4));
            LDSM4(Al, base + (((ch + 4) ^ (row & 7)) << 4));
#pragma unroll
            for (int n = 0; n < 4; n++) {
                const int np = n >> 1, sel = n & 1;
                MMAH(acc[mi][n], Ah, Bh[np][sel], Bh[np][2 + sel]);
                MMAH(acc[mi][n], Al, Bh[np][sel], Bh[np][2 + sel]);
            }
        }
    }
}

#define SMSZ 65536   // 2 stages x (A 16KB + B 16KB); 2 blocks/SM = 128KB

#define ZACC(acc)                                                            \
    _Pragma("unroll") for (int i = 0; i < 4; i++)                            \
    _Pragma("unroll") for (int j = 0; j < 4; j++)                            \
    _Pragma("unroll") for (int k = 0; k < 4; k++) acc[i][j][k] = 0.0f;

// ====================================================================
// split W -> bf16 hi/lo
// ====================================================================
__global__ __launch_bounds__(256) void split_w(
    const float* __restrict__ Wq, const float* __restrict__ Wk,
    const float* __restrict__ Wv)
{
    const int proj = blockIdx.y;
    const float* W = (proj == 0) ? Wq : ((proj == 1) ? Wk : Wv);
    size_t i = ((size_t)blockIdx.x * 256 + threadIdx.x) * 4;
    float4 v = *(const float4*)(W + i);
    __nv_bfloat16 h0,h1,h2,h3,l0,l1,l2,l3;
    sp2(v.x,h0,l0); sp2(v.y,h1,l1); sp2(v.z,h2,l2); sp2(v.w,h3,l3);
    *(uint2*)&g_Wh[proj][i] = make_uint2(pack2(h0,h1), pack2(h2,h3));
    *(uint2*)&g_Wl[proj][i] = make_uint2(pack2(l0,l1), pack2(l2,l3));
}

// ====================================================================
// transpose + split x: [b][c][p] -> [b][p][c] hi/lo (bf16, feeds proj)
// ====================================================================
__global__ void transpose_x(const float* __restrict__ x)
{
    __shared__ float tile[32][33];
    const int b = blockIdx.z, c0 = blockIdx.y * 32, p0 = blockIdx.x * 32;
    const int tx = threadIdx.x, ty = threadIdx.y;
    const float* X = x + ((size_t)b * CIN_ + c0) * P_ + p0;
#pragma unroll
    for (int i = 0; i < 4; i++)
        tile[ty + i * 8][tx] = X[(size_t)(ty + i * 8) * P_ + tx];
    __syncthreads();
#pragma unroll
    for (int i = 0; i < 4; i++) {
        float v = tile[tx][ty + i * 8];
        __nv_bfloat16 h, l; sp2(v, h, l);
        size_t o = ((size_t)b * P_ + p0 + ty + i * 8) * CIN_ + c0 + tx;
        g_xth[o] = h; g_xtl[o] = l;
    }
}

// ====================================================================
// proj HMMA (bf16 3-term): Y = W x.  grid (16 p, 8 o, 24)
// ====================================================================
__global__ __launch_bounds__(256, 2) void proj_hmma()
{
    extern __shared__ __align__(128) char sm[];
    const int t = threadIdx.x, lane = t & 31, wid = t >> 5;
    const int wrow = wid >> 2, wcol = wid & 3;
    const int proj = blockIdx.z >> 3, b = blockIdx.z & 7;
    const int m0 = blockIdx.y * 128, n0 = blockIdx.x * 128;
    const uint32_t sb = s2u(sm);

    const __nv_bfloat16* Ah = g_Wh[proj] + (size_t)m0 * CIN_;
    const __nv_bfloat16* Al = g_Wl[proj] + (size_t)m0 * CIN_;
    const __nv_bfloat16* Bh = g_xth + ((size_t)b * P_ + n0) * CIN_;
    const __nv_bfloat16* Bl = g_xtl + ((size_t)b * P_ + n0) * CIN_;

    float acc[4][4][4];
    ZACC(acc);

    ldstage_p(sb,         Ah, Al, CIN_, t);
    ldstage_p(sb + 16384, Bh, Bl, CIN_, t);
    CP_COMMIT();
    for (int c = 0; c < CIN_ / 32; c++) {
        CP_WAIT0();
        __syncthreads();
        const int buf = c & 1;
        if (c + 1 < CIN_ / 32) {
            const uint32_t nb = sb + (buf ^ 1) * 32768;
            ldstage_p(nb,         Ah + (c + 1) * 32, Al + (c + 1) * 32, CIN_, t);
            ldstage_p(nb + 16384, Bh + (c + 1) * 32, Bl + (c + 1) * 32, CIN_, t);
            CP_COMMIT();
        }
        stage_pp3(sb + buf * 32768, sb + buf * 32768 + 16384, lane, wrow, wcol, acc);
    }

    float* Y = g_Y[proj] + (size_t)b * COUT_ * P_;
    const int rbase = m0 + wrow * 64 + (lane >> 2);
    const int cbase = n0 + wcol * 32 + (lane & 3) * 2;
#pragma unroll
    for (int mi = 0; mi < 4; mi++)
#pragma unroll
        for (int n = 0; n < 4; n++) {
            const int r = rbase + mi * 16, cc = cbase + n * 8;
            *(float2*)&Y[(size_t)r * P_ + cc] =
                make_float2(acc[mi][n][0], acc[mi][n][1]);
            *(float2*)&Y[(size_t)(r + 8) * P_ + cc] =
                make_float2(acc[mi][n][2], acc[mi][n][3]);
        }
}

// ====================================================================
// BN stats (deterministic)
// ====================================================================
__global__ __launch_bounds__(256) void stats_kernel(
    const float* __restrict__ gq, const float* __restrict__ bq,
    const float* __restrict__ gk, const float* __restrict__ bk,
    const float* __restrict__ gv, const float* __restrict__ bv)
{
    const int proj = blockIdx.y, ch = blockIdx.x, t = threadIdx.x;
    const float* Ych = g_Y[proj] + (size_t)ch * P_;
    float s = 0.0f, q = 0.0f;
    for (int b = 0; b < B_; b++) {
        const float* row = Ych + (size_t)b * COUT_ * P_;
        for (int p = t * 4; p < P_; p += 1024) {
            float4 v = *(const float4*)&row[p];
            s += v.x + v.y + v.z + v.w;
            q = fmaf(v.x, v.x, q); q = fmaf(v.y, v.y, q);
            q = fmaf(v.z, v.z, q); q = fmaf(v.w, v.w, q);
        }
    }
    __shared__ float rs[256], rq[256];
    rs[t] = s; rq[t] = q;
    __syncthreads();
    for (int st = 128; st > 0; st >>= 1) {
        if (t < st) { rs[t] += rs[t + st]; rq[t] += rq[t + st]; }
        __syncthreads();
    }
    if (t == 0) {
        const float n = (float)(B_ * P_);
        const float mean = rs[0] / n;
        const float var  = rq[0] / n - mean * mean;
        const float* g  = (proj == 0) ? gq : ((proj == 1) ? gk : gv);
        const float* be = (proj == 0) ? bq : ((proj == 1) ? bk : bv);
        const float a = g[ch] * rsqrtf(var + EPS_);
        g_a[proj][ch]   = a;
        g_bsh[proj][ch] = be[ch] - mean * a;
    }
}

// ====================================================================
// finalize Q: BN+lrelu, fp16 hi/lo split, keep [o][p]
// ====================================================================
__global__ __launch_bounds__(256) void fin_q()
{
    const int b = blockIdx.z, o = blockIdx.y;
    const float a = g_a[0][o], bs = g_bsh[0][o];
    const size_t off = ((size_t)b * COUT_ + o) * P_ + blockIdx.x * 1024 + threadIdx.x * 4;
    float4 v = *(const float4*)&g_Y[0][off];
    v.x = lrelu(fmaf(a, v.x, bs)); v.y = lrelu(fmaf(a, v.y, bs));
    v.z = lrelu(fmaf(a, v.z, bs)); v.w = lrelu(fmaf(a, v.w, bs));
    __half h0,h1,h2,h3,l0,l1,l2,l3;
    sp2h(v.x,h0,l0); sp2h(v.y,h1,l1); sp2h(v.z,h2,l2); sp2h(v.w,h3,l3);
    *(uint2*)&g_Qh[off] = make_uint2(pack2h(h0,h1), pack2h(h2,h3));
    *(uint2*)&g_Ql[off] = make_uint2(pack2h(l0,l1), pack2h(l2,l3));
}

// ====================================================================
// finalize K/V: BN+lrelu + transpose to [b][p][o] fp16.
// K: hi only.  V: hi/lo split.
// ====================================================================
__global__ void fin_kv()
{
    __shared__ float tile[32][33];
    const int z = blockIdx.z, pv = z >> 3, b = z & 7, proj = 1 + pv;
    const int o0 = blockIdx.y * 32, p0 = blockIdx.x * 32;
    const int tx = threadIdx.x, ty = threadIdx.y;
    const float* Y = g_Y[proj] + ((size_t)b * COUT_ + o0) * P_ + p0;
#pragma unroll
    for (int i = 0; i < 4; i++) {
        const int oo = ty + i * 8;
        const float a = g_a[proj][o0 + oo], bs = g_bsh[proj][o0 + oo];
        tile[oo][tx] = lrelu(fmaf(a, Y[(size_t)oo * P_ + tx], bs));
    }
    __syncthreads();
    if (pv == 0) {
#pragma unroll
        for (int i = 0; i < 4; i++) {
            float v = tile[tx][ty + i * 8];
            size_t o = ((size_t)b * P_ + p0 + ty + i * 8) * COUT_ + o0 + tx;
            g_Kth[o] = __float2half_rn(v);
        }
    } else {
#pragma unroll
        for (int i = 0; i < 4; i++) {
            float v = tile[tx][ty + i * 8];
            __half h, l; sp2h(v, h, l);
            size_t o = ((size_t)b * P_ + p0 + ty + i * 8) * COUT_ + o0 + tx;
            g_Vth[o] = h; g_Vtl[o] = l;
        }
    }
}

// ====================================================================
// attn HMMA (fp16 2-term): logits = K^T V, exp + E(fp16) + row sums.
// grid (16 j, 16 i, 64 bh)
// ====================================================================
__global__ __launch_bounds__(256, 2) void attn_hmma()
{
    extern __shared__ __align__(128) char sm[];
    __shared__ float ps[2][64][4];
    const int t = threadIdx.x, lane = t & 31, wid = t >> 5;
    const int wrow = wid >> 2, wcol = wid & 3;
    const int bh = blockIdx.z, b = bh >> 3, h = bh & 7;
    const int i0 = blockIdx.y * 128, j0 = blockIdx.x * 128;
    const uint32_t sb = s2u(sm);

    const size_t hoff = (size_t)h * DH_;
    const __half* Ah = g_Kth + ((size_t)b * P_ + i0) * COUT_ + hoff;
    const __half* Bh = g_Vth + ((size_t)b * P_ + j0) * COUT_ + hoff;
    const __half* Bl = g_Vtl + ((size_t)b * P_ + j0) * COUT_ + hoff;

    float acc[4][4][4];
    ZACC(acc);

    ldstage_s(sb,         Ah, COUT_, t);
    ldstage_p(sb + 16384, Bh, Bl, COUT_, t);
    CP_COMMIT();
    for (int c = 0; c < DH_ / 32; c++) {
        CP_WAIT0();
        __syncthreads();
        const int buf = c & 1;
        if (c + 1 < DH_ / 32) {
            const uint32_t nb = sb + (buf ^ 1) * 32768;
            ldstage_s(nb,         Ah + (c + 1) * 32, COUT_, t);
            ldstage_p(nb + 16384, Bh + (c + 1) * 32, Bl + (c + 1) * 32, COUT_, t);
            CP_COMMIT();
        }
        stage_sp2(sb + buf * 32768, sb + buf * 32768 + 16384, lane, wrow, wcol, acc);
    }

    const float scale = 0.08838834764831845f;  // 1/sqrt(128)
    const int lrow = lane >> 2;
    const int ccol = j0 + wcol * 32 + (lane & 3) * 2;
#pragma unroll
    for (int mi = 0; mi < 4; mi++) {
        const int r = i0 + wrow * 64 + mi * 16 + lrow;
        uint32_t* eh0 = (uint32_t*)(g_E + ((size_t)bh * P_ + r) * P_);
        uint32_t* eh1 = (uint32_t*)(g_E + ((size_t)bh * P_ + r + 8) * P_);
        float sa = 0.0f, sb2 = 0.0f;
#pragma unroll
        for (int n = 0; n < 4; n++) {
            const int cw = (ccol + n * 8) >> 1;
            float e0 = __expf(acc[mi][n][0] * scale);
            float e1 = __expf(acc[mi][n][1] * scale);
            float e2 = __expf(acc[mi][n][2] * scale);
            float e3 = __expf(acc[mi][n][3] * scale);
            sa  += e0 + e1;
            sb2 += e2 + e3;
            eh0[cw] = pack2h(__float2half_rn(e0), __float2half_rn(e1));
            eh1[cw] = pack2h(__float2half_rn(e2), __float2half_rn(e3));
        }
        sa  += __shfl_xor_sync(0xFFFFFFFFu, sa, 1);
        sa  += __shfl_xor_sync(0xFFFFFFFFu, sa, 2);
        sb2 += __shfl_xor_sync(0xFFFFFFFFu, sb2, 1);
        sb2 += __shfl_xor_sync(0xFFFFFFFFu, sb2, 2);
        if ((lane & 3) == 0) {
            ps[wrow][mi * 16 + lrow][wcol]     = sa;
            ps[wrow][mi * 16 + lrow + 8][wcol] = sb2;
        }
    }
    __syncthreads();
    if (t < 128) {
        const int wr = t >> 6, rr = t & 63;
        float s = ps[wr][rr][0] + ps[wr][rr][1] + ps[wr][rr][2] + ps[wr][rr][3];
        g_psum[((size_t)bh * P_ + i0 + wr * 64 + rr) * 16 + blockIdx.x] = s;
    }
}

// ====================================================================
// reduce partial sums -> 1/rowsum
// ====================================================================
__global__ __launch_bounds__(256) void red_psum()
{
    const size_t r = (size_t)blockIdx.x * 256 + threadIdx.x;
    const float4* p = (const float4*)(g_psum + r * 16);
    float4 a = p[0], b = p[1], c = p[2], d = p[3];
    float s = a.x + a.y + a.z + a.w + b.x + b.y + b.z + b.w
            + c.x + c.y + c.z + c.w + d.x + d.y + d.z + d.w;
    g_rsinv[r] = 1.0f / s;
}

// ====================================================================
// out HMMA (fp16 2-term): out[c][i] = rsinv[i] * sum_j Q[c][j] E[i][j]
// grid (16 i-tiles, 1, 64 bh)
// ====================================================================
__global__ __launch_bounds__(256, 2) void out_hmma(float* __restrict__ out)
{
    extern __shared__ __align__(128) char sm[];
    const int t = threadIdx.x, lane = t & 31, wid = t >> 5;
    const int wrow = wid >> 2, wcol = wid & 3;
    const int bh = blockIdx.z, b = bh >> 3, h = bh & 7;
    const int n0 = blockIdx.x * 128;
    const uint32_t sb = s2u(sm);

    const __half* Ah = g_Qh + ((size_t)b * COUT_ + h * DH_) * P_;
    const __half* Al = g_Ql + ((size_t)b * COUT_ + h * DH_) * P_;
    const __half* Bh = g_E  + ((size_t)bh * P_ + n0) * P_;

    float acc[4][4][4];
    ZACC(acc);

    ldstage_p(sb,         Ah, Al, P_, t);
    ldstage_s(sb + 16384, Bh, P_, t);
    CP_COMMIT();
    for (int c = 0; c < P_ / 32; c++) {
        CP_WAIT0();
        __syncthreads();
        const int buf = c & 1;
        if (c + 1 < P_ / 32) {
            const uint32_t nb = sb + (buf ^ 1) * 32768;
            ldstage_p(nb,         Ah + (c + 1) * 32, Al + (c + 1) * 32, P_, t);
            ldstage_s(nb + 16384, Bh + (c + 1) * 32, P_, t);
            CP_COMMIT();
        }
        stage_ps2(sb + buf * 32768, sb + buf * 32768 + 16384, lane, wrow, wcol, acc);
    }

    const float* inv = g_rsinv + (size_t)bh * P_;
    const int rbase = h * DH_ + wrow * 64 + (lane >> 2);
    const int cbase = n0 + wcol * 32 + (lane & 3) * 2;
#pragma unroll
    for (int mi = 0; mi < 4; mi++)
#pragma unroll
        for (int n = 0; n < 4; n++) {
            const int r = rbase + mi * 16, cc = cbase + n * 8;
            const float i0v = inv[cc], i1v = inv[cc + 1];
            float* o0 = out + ((size_t)b * COUT_ + r) * P_ + cc;
            float* o1 = out + ((size_t)b * COUT_ + r + 8) * P_ + cc;
            *(float2*)o0 = make_float2(acc[mi][n][0] * i0v, acc[mi][n][1] * i1v);
            *(float2*)o1 = make_float2(acc[mi][n][2] * i0v, acc[mi][n][3] * i1v);
        }
}

// ====================================================================
extern "C" void kernel_launch(void* const* d_in, const int* in_sizes, int n_in,
                              void* d_out, int out_size)
{
    const float* x  = (const float*)d_in[0];
    const float* Wq = (const float*)d_in[1];
    const float* gq = (const float*)d_in[2];
    const float* bq = (const float*)d_in[3];
    const float* Wk = (const float*)d_in[4];
    const float* gk = (const float*)d_in[5];
    const float* bk = (const float*)d_in[6];
    const float* Wv = (const float*)d_in[7];
    const float* gv = (const float*)d_in[8];
    const float* bv = (const float*)d_in[9];
    float* out = (float*)d_out;

    cudaFuncSetAttribute(proj_hmma, cudaFuncAttributeMaxDynamicSharedMemorySize, SMSZ);
    cudaFuncSetAttribute(attn_hmma, cudaFuncAttributeMaxDynamicSharedMemorySize, SMSZ);
    cudaFuncSetAttribute(out_hmma,  cudaFuncAttributeMaxDynamicSharedMemorySize, SMSZ);

    split_w     <<< dim3(512, 3), 256 >>>(Wq, Wk, Wv);
    transpose_x <<< dim3(64, 16, 8), dim3(32, 8) >>>(x);
    proj_hmma   <<< dim3(16, 8, 24), 256, SMSZ >>>();
    stats_kernel<<< dim3(COUT_, 3), 256 >>>(gq, bq, gk, bk, gv, bv);
    fin_q       <<< dim3(2, COUT_, B_), 256 >>>();
    fin_kv      <<< dim3(64, 32, 16), dim3(32, 8) >>>();
    attn_hmma   <<< dim3(16, 16, NBH_), 256, SMSZ >>>();
    red_psum    <<< 512, 256 >>>();
    out_hmma    <<< dim3(16, 1, NBH_), 256, SMSZ >>>(out);
}

// round 17
// speedup vs baseline: 4.1897x; 1.2819x over previous
#include <cuda_runtime.h>
#include <cuda_fp16.h>
#include <cstdint>

#define B_    8
#define CIN_  512
#define COUT_ 1024
#define P_    2048
#define H_    8
#define DH_   128
#define NBH_  64
#define EPS_  1e-5f

// ---------------- scratch (device globals; no allocation) ----------------
__device__ float  g_Y[3][(size_t)B_ * COUT_ * P_];    // raw projections (fp32)
__device__ __half g_Wh[3][(size_t)COUT_ * CIN_];      // W fp16 hi
__device__ __half g_Wl[3][(size_t)COUT_ * CIN_];      // W fp16 lo
__device__ __half g_xt[(size_t)B_ * P_ * CIN_];       // x^T [b][p][c] fp16 single
__device__ __half g_Q[(size_t)B_ * COUT_ * P_];       // BN+lrelu Q [o][p] fp16 single
__device__ __half g_Kth[(size_t)B_ * P_ * COUT_];     // BN+lrelu K^T [p][o] fp16 single
__device__ __half g_Vth[(size_t)B_ * P_ * COUT_];     // V^T fp16 hi
__device__ __half g_Vtl[(size_t)B_ * P_ * COUT_];     // V^T fp16 lo
__device__ __half g_E[(size_t)NBH_ * P_ * P_];        // exp(logits) fp16 single
__device__ float  g_psum[(size_t)NBH_ * P_ * 16];     // attn partial row sums
__device__ float2 g_pstat[(size_t)3 * COUT_ * 128];   // proj partial (sum, sumsq)
__device__ float  g_a[3][COUT_];
__device__ float  g_bsh[3][COUT_];
__device__ float  g_rsinv[NBH_ * P_];

// ---------------- helpers ----------------
__device__ __forceinline__ float lrelu(float v) { return fmaxf(v, 0.1f * v); }

__device__ __forceinline__ uint32_t s2u(const void* p) {
    uint32_t a;
    asm("{ .reg .u64 t; cvta.to.shared.u64 t, %1; cvt.u32.u64 %0, t; }" : "=r"(a) : "l"(p));
    return a;
}
__device__ __forceinline__ void sp2h(float v, __half& h, __half& l) {
    h = __float2half_rn(v);
    l = __float2half_rn(v - __half2float(h));
}
__device__ __forceinline__ uint32_t pack2h(__half a, __half b) {
    uint16_t ua = *(uint16_t*)&a, ub = *(uint16_t*)&b;
    return (uint32_t)ua | ((uint32_t)ub << 16);
}

// ---------------- HMMA building blocks (base-target ISA, sm_80+) --------
#define LDSM4(r, a)                                                          \
    asm volatile("ldmatrix.sync.aligned.m8n8.x4.shared.b16 {%0,%1,%2,%3}, [%4];" \
        : "=r"((r)[0]), "=r"((r)[1]), "=r"((r)[2]), "=r"((r)[3]) : "r"(a))

#define MMAH(c, a, b0, b1)                                                   \
    asm volatile("mma.sync.aligned.m16n8k16.row.col.f32.f16.f16.f32 "        \
        "{%0,%1,%2,%3},{%4,%5,%6,%7},{%8,%9},{%0,%1,%2,%3};"                 \
        : "+f"((c)[0]), "+f"((c)[1]), "+f"((c)[2]), "+f"((c)[3])             \
        : "r"((a)[0]), "r"((a)[1]), "r"((a)[2]), "r"((a)[3]),                \
          "r"(b0), "r"(b1))

__device__ __forceinline__ void cpa16(uint32_t dst, const void* src) {
    asm volatile("cp.async.cg.shared.global [%0], [%1], 16;" :: "r"(dst), "l"(src));
}
#define CP_COMMIT() asm volatile("cp.async.commit_group;" ::: "memory")
#define CP_WAIT0()  asm volatile("cp.async.wait_group 0;" ::: "memory")

// Stage tile: 128 rows x 128B, 8 x 16B chunks per row, chunk position
// swizzled pos = chunk ^ (row & 7)  -> LDSM conflict-free.
// ldstage_p: fills chunks 0-3 from `hi` and 4-7 from `lo` (two operands may
// share one tile).  ldstage_s: chunks 0-3 only.
template <typename T>
__device__ __forceinline__ void ldstage_p(uint32_t sdst, const T* hi,
                                          const T* lo, size_t ld, int t) {
#pragma unroll
    for (int i = 0; i < 2; i++) {
        const int id  = t + i * 256;         // 0..511
        const int row = id >> 2, ch = id & 3;
        const uint32_t base = sdst + row * 128;
        cpa16(base + ((ch ^ (row & 7)) << 4),       hi + (size_t)row * ld + ch * 8);
        cpa16(base + (((ch + 4) ^ (row & 7)) << 4), lo + (size_t)row * ld + ch * 8);
    }
}
template <typename T>
__device__ __forceinline__ void ldstage_s(uint32_t sdst, const T* hi,
                                          size_t ld, int t) {
#pragma unroll
    for (int i = 0; i < 2; i++) {
        const int id  = t + i * 256;
        const int row = id >> 2, ch = id & 3;
        cpa16(sdst + row * 128 + ((ch ^ (row & 7)) << 4),
              hi + (size_t)row * ld + ch * 8);
    }
}

// ---- fp16 2-term stage: A single x B pair (attn: K x V) ----
__device__ __forceinline__ void stage_sp2(uint32_t sA, uint32_t sB,
                                          int lane, int wrow, int wcol,
                                          float acc[4][4][4]) {
    const int rA = wrow * 64 + (lane & 15);
    const int rB = wcol * 32 + (lane & 15);
    const int hc = lane >> 4;
#pragma unroll
    for (int ks = 0; ks < 2; ks++) {
        const int ch = ks * 2 + hc;
        uint32_t Bh[2][4], Bl[2][4];
#pragma unroll
        for (int np = 0; np < 2; np++) {
            const int row = rB + np * 16;
            const uint32_t base = sB + row * 128;
            LDSM4(Bh[np], base + ((ch ^ (row & 7)) << 4));
            LDSM4(Bl[np], base + (((ch + 4) ^ (row & 7)) << 4));
        }
#pragma unroll
        for (int mi = 0; mi < 4; mi++) {
            uint32_t Ah[4];
            const int row = rA + mi * 16;
            LDSM4(Ah, sA + row * 128 + ((ch ^ (row & 7)) << 4));
#pragma unroll
            for (int n = 0; n < 4; n++) {
                const int np = n >> 1, sel = n & 1;
                MMAH(acc[mi][n], Ah, Bh[np][sel], Bh[np][2 + sel]);
                MMAH(acc[mi][n], Ah, Bl[np][sel], Bl[np][2 + sel]);
            }
        }
    }
}

// ---- fp16 2-term stage: A pair x B single (proj: W x X) ----
__device__ __forceinline__ void stage_ps2(uint32_t sA, uint32_t sB,
                                          int lane, int wrow, int wcol,
                                          float acc[4][4][4]) {
    const int rA = wrow * 64 + (lane & 15);
    const int rB = wcol * 32 + (lane & 15);
    const int hc = lane >> 4;
#pragma unroll
    for (int ks = 0; ks < 2; ks++) {
        const int ch = ks * 2 + hc;
        uint32_t Bh[2][4];
#pragma unroll
        for (int np = 0; np < 2; np++) {
            const int row = rB + np * 16;
            LDSM4(Bh[np], sB + row * 128 + ((ch ^ (row & 7)) << 4));
        }
#pragma unroll
        for (int mi = 0; mi < 4; mi++) {
            uint32_t Ah[4], Al[4];
            const int row = rA + mi * 16;
            const uint32_t base = sA + row * 128;
            LDSM4(Ah, base + ((ch ^ (row & 7)) << 4));
            LDSM4(Al, base + (((ch + 4) ^ (row & 7)) << 4));
#pragma unroll
            for (int n = 0; n < 4; n++) {
                const int np = n >> 1, sel = n & 1;
                MMAH(acc[mi][n], Ah, Bh[np][sel], Bh[np][2 + sel]);
                MMAH(acc[mi][n], Al, Bh[np][sel], Bh[np][2 + sel]);
            }
        }
    }
}

// ---- fp16 1-term stage, packed tile: A in chunks 0-3, B in chunks 4-7 ----
__device__ __forceinline__ void stage_ab1(uint32_t sT,
                                          int lane, int wrow, int wcol,
                                          float acc[4][4][4]) {
    const int rA = wrow * 64 + (lane & 15);
    const int rB = wcol * 32 + (lane & 15);
    const int hc = lane >> 4;
#pragma unroll
    for (int ks = 0; ks < 2; ks++) {
        const int ch = ks * 2 + hc;
        uint32_t Bh[2][4];
#pragma unroll
        for (int np = 0; np < 2; np++) {
            const int row = rB + np * 16;
            LDSM4(Bh[np], sT + row * 128 + (((ch + 4) ^ (row & 7)) << 4));
        }
#pragma unroll
        for (int mi = 0; mi < 4; mi++) {
            uint32_t Ah[4];
            const int row = rA + mi * 16;
            LDSM4(Ah, sT + row * 128 + ((ch ^ (row & 7)) << 4));
#pragma unroll
            for (int n = 0; n < 4; n++) {
                const int np = n >> 1, sel = n & 1;
                MMAH(acc[mi][n], Ah, Bh[np][sel], Bh[np][2 + sel]);
            }
        }
    }
}

#define SMSZ  65536   // proj/attn: 2 stages x (A 16KB + B 16KB)
#define SMSZO 32768   // out: 2 stages x 16KB packed A|B tile

#define ZACC(acc)                                                            \
    _Pragma("unroll") for (int i = 0; i < 4; i++)                            \
    _Pragma("unroll") for (int j = 0; j < 4; j++)                            \
    _Pragma("unroll") for (int k = 0; k < 4; k++) acc[i][j][k] = 0.0f;

// ====================================================================
// split W -> fp16 hi/lo
// ====================================================================
__global__ __launch_bounds__(256) void split_w(
    const float* __restrict__ Wq, const float* __restrict__ Wk,
    const float* __restrict__ Wv)
{
    const int proj = blockIdx.y;
    const float* W = (proj == 0) ? Wq : ((proj == 1) ? Wk : Wv);
    size_t i = ((size_t)blockIdx.x * 256 + threadIdx.x) * 4;
    float4 v = *(const float4*)(W + i);
    __half h0,h1,h2,h3,l0,l1,l2,l3;
    sp2h(v.x,h0,l0); sp2h(v.y,h1,l1); sp2h(v.z,h2,l2); sp2h(v.w,h3,l3);
    *(uint2*)&g_Wh[proj][i] = make_uint2(pack2h(h0,h1), pack2h(h2,h3));
    *(uint2*)&g_Wl[proj][i] = make_uint2(pack2h(l0,l1), pack2h(l2,l3));
}

// ====================================================================
// transpose x: [b][c][p] -> [b][p][c] fp16 single
// ====================================================================
__global__ void transpose_x(const float* __restrict__ x)
{
    __shared__ float tile[32][33];
    const int b = blockIdx.z, c0 = blockIdx.y * 32, p0 = blockIdx.x * 32;
    const int tx = threadIdx.x, ty = threadIdx.y;
    const float* X = x + ((size_t)b * CIN_ + c0) * P_ + p0;
#pragma unroll
    for (int i = 0; i < 4; i++)
        tile[ty + i * 8][tx] = X[(size_t)(ty + i * 8) * P_ + tx];
    __syncthreads();
#pragma unroll
    for (int i = 0; i < 4; i++) {
        float v = tile[tx][ty + i * 8];
        g_xt[((size_t)b * P_ + p0 + ty + i * 8) * CIN_ + c0 + tx] = __float2half_rn(v);
    }
}

// ====================================================================
// proj HMMA (fp16 2-term, W pair x X single): Y = W x + fused stats
// grid (16 p, 8 o, 24 = proj*8+b)
// ====================================================================
__global__ __launch_bounds__(256, 2) void proj_hmma()
{
    extern __shared__ __align__(128) char sm[];
    __shared__ float pss[128][4], psq[128][4];
    const int t = threadIdx.x, lane = t & 31, wid = t >> 5;
    const int wrow = wid >> 2, wcol = wid & 3;
    const int proj = blockIdx.z >> 3, b = blockIdx.z & 7;
    const int m0 = blockIdx.y * 128, n0 = blockIdx.x * 128;
    const uint32_t sb = s2u(sm);

    const __half* Ah = g_Wh[proj] + (size_t)m0 * CIN_;
    const __half* Al = g_Wl[proj] + (size_t)m0 * CIN_;
    const __half* Bh = g_xt + ((size_t)b * P_ + n0) * CIN_;

    float acc[4][4][4];
    ZACC(acc);

    ldstage_p(sb,         Ah, Al, CIN_, t);
    ldstage_s(sb + 16384, Bh, CIN_, t);
    CP_COMMIT();
    for (int c = 0; c < CIN_ / 32; c++) {
        CP_WAIT0();
        __syncthreads();
        const int buf = c & 1;
        if (c + 1 < CIN_ / 32) {
            const uint32_t nb = sb + (buf ^ 1) * 32768;
            ldstage_p(nb,         Ah + (c + 1) * 32, Al + (c + 1) * 32, CIN_, t);
            ldstage_s(nb + 16384, Bh + (c + 1) * 32, CIN_, t);
            CP_COMMIT();
        }
        stage_ps2(sb + buf * 32768, sb + buf * 32768 + 16384, lane, wrow, wcol, acc);
    }

    float* Y = g_Y[proj] + (size_t)b * COUT_ * P_;
    const int rbase = m0 + wrow * 64 + (lane >> 2);
    const int cbase = n0 + wcol * 32 + (lane & 3) * 2;
#pragma unroll
    for (int mi = 0; mi < 4; mi++)
#pragma unroll
        for (int n = 0; n < 4; n++) {
            const int r = rbase + mi * 16, cc = cbase + n * 8;
            *(float2*)&Y[(size_t)r * P_ + cc] =
                make_float2(acc[mi][n][0], acc[mi][n][1]);
            *(float2*)&Y[(size_t)(r + 8) * P_ + cc] =
                make_float2(acc[mi][n][2], acc[mi][n][3]);
        }

    // fused per-channel partial stats over this block's 128 columns
#pragma unroll
    for (int mi = 0; mi < 4; mi++) {
        float s0 = 0.f, q0 = 0.f, s1 = 0.f, q1 = 0.f;
#pragma unroll
        for (int n = 0; n < 4; n++) {
            float a0 = acc[mi][n][0], a1 = acc[mi][n][1];
            float a2 = acc[mi][n][2], a3 = acc[mi][n][3];
            s0 += a0 + a1; q0 = fmaf(a0, a0, fmaf(a1, a1, q0));
            s1 += a2 + a3; q1 = fmaf(a2, a2, fmaf(a3, a3, q1));
        }
        s0 += __shfl_xor_sync(~0u, s0, 1); s0 += __shfl_xor_sync(~0u, s0, 2);
        q0 += __shfl_xor_sync(~0u, q0, 1); q0 += __shfl_xor_sync(~0u, q0, 2);
        s1 += __shfl_xor_sync(~0u, s1, 1); s1 += __shfl_xor_sync(~0u, s1, 2);
        q1 += __shfl_xor_sync(~0u, q1, 1); q1 += __shfl_xor_sync(~0u, q1, 2);
        if ((lane & 3) == 0) {
            const int r = wrow * 64 + mi * 16 + (lane >> 2);
            pss[r][wcol] = s0;  psq[r][wcol] = q0;
            pss[r + 8][wcol] = s1;  psq[r + 8][wcol] = q1;
        }
    }
    __syncthreads();
    if (t < 128) {
        float s = pss[t][0] + pss[t][1] + pss[t][2] + pss[t][3];
        float q = psq[t][0] + psq[t][1] + psq[t][2] + psq[t][3];
        g_pstat[((size_t)proj * COUT_ + m0 + t) * 128 + b * 16 + blockIdx.x] =
            make_float2(s, q);
    }
}

// ====================================================================
// reduce proj partial stats -> BN affine params.  grid (1024, 3), 128 thr
// ====================================================================
__global__ __launch_bounds__(128) void stats_red(
    const float* __restrict__ gq, const float* __restrict__ bq,
    const float* __restrict__ gk, const float* __restrict__ bk,
    const float* __restrict__ gv, const float* __restrict__ bv)
{
    const int proj = blockIdx.y, ch = blockIdx.x, t = threadIdx.x;
    float2 v = g_pstat[((size_t)proj * COUT_ + ch) * 128 + t];
    __shared__ float rs[128], rq[128];
    rs[t] = v.x; rq[t] = v.y;
    __syncthreads();
    for (int st = 64; st > 0; st >>= 1) {
        if (t < st) { rs[t] += rs[t + st]; rq[t] += rq[t + st]; }
        __syncthreads();
    }
    if (t == 0) {
        const float n = (float)(B_ * P_);
        const float mean = rs[0] / n;
        const float var  = rq[0] / n - mean * mean;
        const float* g  = (proj == 0) ? gq : ((proj == 1) ? gk : gv);
        const float* be = (proj == 0) ? bq : ((proj == 1) ? bk : bv);
        const float a = g[ch] * rsqrtf(var + EPS_);
        g_a[proj][ch]   = a;
        g_bsh[proj][ch] = be[ch] - mean * a;
    }
}

// ====================================================================
// finalize Q: BN+lrelu, fp16 single, keep [o][p]
// ====================================================================
__global__ __launch_bounds__(256) void fin_q()
{
    const int b = blockIdx.z, o = blockIdx.y;
    const float a = g_a[0][o], bs = g_bsh[0][o];
    const size_t off = ((size_t)b * COUT_ + o) * P_ + blockIdx.x * 1024 + threadIdx.x * 4;
    float4 v = *(const float4*)&g_Y[0][off];
    v.x = lrelu(fmaf(a, v.x, bs)); v.y = lrelu(fmaf(a, v.y, bs));
    v.z = lrelu(fmaf(a, v.z, bs)); v.w = lrelu(fmaf(a, v.w, bs));
    *(uint2*)&g_Q[off] = make_uint2(
        pack2h(__float2half_rn(v.x), __float2half_rn(v.y)),
        pack2h(__float2half_rn(v.z), __float2half_rn(v.w)));
}

// ====================================================================
// finalize K/V: BN+lrelu + transpose to [b][p][o] fp16.
// K: single.  V: hi/lo pair.
// ====================================================================
__global__ void fin_kv()
{
    __shared__ float tile[32][33];
    const int z = blockIdx.z, pv = z >> 3, b = z & 7, proj = 1 + pv;
    const int o0 = blockIdx.y * 32, p0 = blockIdx.x * 32;
    const int tx = threadIdx.x, ty = threadIdx.y;
    const float* Y = g_Y[proj] + ((size_t)b * COUT_ + o0) * P_ + p0;
#pragma unroll
    for (int i = 0; i < 4; i++) {
        const int oo = ty + i * 8;
        const float a = g_a[proj][o0 + oo], bs = g_bsh[proj][o0 + oo];
        tile[oo][tx] = lrelu(fmaf(a, Y[(size_t)oo * P_ + tx], bs));
    }
    __syncthreads();
    if (pv == 0) {
#pragma unroll
        for (int i = 0; i < 4; i++) {
            float v = tile[tx][ty + i * 8];
            g_Kth[((size_t)b * P_ + p0 + ty + i * 8) * COUT_ + o0 + tx] =
                __float2half_rn(v);
        }
    } else {
#pragma unroll
        for (int i = 0; i < 4; i++) {
            float v = tile[tx][ty + i * 8];
            __half h, l; sp2h(v, h, l);
            size_t o = ((size_t)b * P_ + p0 + ty + i * 8) * COUT_ + o0 + tx;
            g_Vth[o] = h; g_Vtl[o] = l;
        }
    }
}

// ====================================================================
// attn HMMA (fp16 2-term): logits = K^T V, exp + E(fp16) + row sums.
// grid (16 j, 16 i, 64 bh)
// ====================================================================
__global__ __launch_bounds__(256, 2) void attn_hmma()
{
    extern __shared__ __align__(128) char sm[];
    __shared__ float ps[2][64][4];
    const int t = threadIdx.x, lane = t & 31, wid = t >> 5;
    const int wrow = wid >> 2, wcol = wid & 3;
    const int bh = blockIdx.z, b = bh >> 3, h = bh & 7;
    const int i0 = blockIdx.y * 128, j0 = blockIdx.x * 128;
    const uint32_t sb = s2u(sm);

    const size_t hoff = (size_t)h * DH_;
    const __half* Ah = g_Kth + ((size_t)b * P_ + i0) * COUT_ + hoff;
    const __half* Bh = g_Vth + ((size_t)b * P_ + j0) * COUT_ + hoff;
    const __half* Bl = g_Vtl + ((size_t)b * P_ + j0) * COUT_ + hoff;

    float acc[4][4][4];
    ZACC(acc);

    ldstage_s(sb,         Ah, COUT_, t);
    ldstage_p(sb + 16384, Bh, Bl, COUT_, t);
    CP_COMMIT();
    for (int c = 0; c < DH_ / 32; c++) {
        CP_WAIT0();
        __syncthreads();
        const int buf = c & 1;
        if (c + 1 < DH_ / 32) {
            const uint32_t nb = sb + (buf ^ 1) * 32768;
            ldstage_s(nb,         Ah + (c + 1) * 32, COUT_, t);
            ldstage_p(nb + 16384, Bh + (c + 1) * 32, Bl + (c + 1) * 32, COUT_, t);
            CP_COMMIT();
        }
        stage_sp2(sb + buf * 32768, sb + buf * 32768 + 16384, lane, wrow, wcol, acc);
    }

    const float scale = 0.08838834764831845f;  // 1/sqrt(128)
    const int lrow = lane >> 2;
    const int ccol = j0 + wcol * 32 + (lane & 3) * 2;
#pragma unroll
    for (int mi = 0; mi < 4; mi++) {
        const int r = i0 + wrow * 64 + mi * 16 + lrow;
        uint32_t* eh0 = (uint32_t*)(g_E + ((size_t)bh * P_ + r) * P_);
        uint32_t* eh1 = (uint32_t*)(g_E + ((size_t)bh * P_ + r + 8) * P_);
        float sa = 0.0f, sb2 = 0.0f;
#pragma unroll
        for (int n = 0; n < 4; n++) {
            const int cw = (ccol + n * 8) >> 1;
            float e0 = __expf(acc[mi][n][0] * scale);
            float e1 = __expf(acc[mi][n][1] * scale);
            float e2 = __expf(acc[mi][n][2] * scale);
            float e3 = __expf(acc[mi][n][3] * scale);
            sa  += e0 + e1;
            sb2 += e2 + e3;
            eh0[cw] = pack2h(__float2half_rn(e0), __float2half_rn(e1));
            eh1[cw] = pack2h(__float2half_rn(e2), __float2half_rn(e3));
        }
        sa  += __shfl_xor_sync(0xFFFFFFFFu, sa, 1);
        sa  += __shfl_xor_sync(0xFFFFFFFFu, sa, 2);
        sb2 += __shfl_xor_sync(0xFFFFFFFFu, sb2, 1);
        sb2 += __shfl_xor_sync(0xFFFFFFFFu, sb2, 2);
        if ((lane & 3) == 0) {
            ps[wrow][mi * 16 + lrow][wcol]     = sa;
            ps[wrow][mi * 16 + lrow + 8][wcol] = sb2;
        }
    }
    __syncthreads();
    if (t < 128) {
        const int wr = t >> 6, rr = t & 63;
        float s = ps[wr][rr][0] + ps[wr][rr][1] + ps[wr][rr][2] + ps[wr][rr][3];
        g_psum[((size_t)bh * P_ + i0 + wr * 64 + rr) * 16 + blockIdx.x] = s;
    }
}

// ====================================================================
// reduce partial sums -> 1/rowsum
// ====================================================================
__global__ __launch_bounds__(256) void red_psum()
{
    const size_t r = (size_t)blockIdx.x * 256 + threadIdx.x;
    const float4* p = (const float4*)(g_psum + r * 16);
    float4 a = p[0], b = p[1], c = p[2], d = p[3];
    float s = a.x + a.y + a.z + a.w + b.x + b.y + b.z + b.w
            + c.x + c.y + c.z + c.w + d.x + d.y + d.z + d.w;
    g_rsinv[r] = 1.0f / s;
}

// ====================================================================
// out HMMA (fp16 1-term, packed tile): out[c][i]=rsinv[i]*sum_j Q[c][j]E[i][j]
// grid (16 i-tiles, 1, 64 bh)
// ====================================================================
__global__ __launch_bounds__(256, 2) void out_hmma(float* __restrict__ out)
{
    extern __shared__ __align__(128) char sm[];
    const int t = threadIdx.x, lane = t & 31, wid = t >> 5;
    const int wrow = wid >> 2, wcol = wid & 3;
    const int bh = blockIdx.z, b = bh >> 3, h = bh & 7;
    const int n0 = blockIdx.x * 128;
    const uint32_t sb = s2u(sm);

    const __half* Ah = g_Q + ((size_t)b * COUT_ + h * DH_) * P_;
    const __half* Bh = g_E + ((size_t)bh * P_ + n0) * P_;

    float acc[4][4][4];
    ZACC(acc);

    ldstage_p(sb, Ah, Bh, P_, t);   // A -> chunks 0-3, B -> chunks 4-7
    CP_COMMIT();
    for (int c = 0; c < P_ / 32; c++) {
        CP_WAIT0();
        __syncthreads();
        const int buf = c & 1;
        if (c + 1 < P_ / 32) {
            ldstage_p(sb + (buf ^ 1) * 16384,
                      Ah + (c + 1) * 32, Bh + (c + 1) * 32, P_, t);
            CP_COMMIT();
        }
        stage_ab1(sb + buf * 16384, lane, wrow, wcol, acc);
    }

    const float* inv = g_rsinv + (size_t)bh * P_;
    const int rbase = h * DH_ + wrow * 64 + (lane >> 2);
    const int cbase = n0 + wcol * 32 + (lane & 3) * 2;
#pragma unroll
    for (int mi = 0; mi < 4; mi++)
#pragma unroll
        for (int n = 0; n < 4; n++) {
            const int r = rbase + mi * 16, cc = cbase + n * 8;
            const float i0v = inv[cc], i1v = inv[cc + 1];
            float* o0 = out + ((size_t)b * COUT_ + r) * P_ + cc;
            float* o1 = out + ((size_t)b * COUT_ + r + 8) * P_ + cc;
            *(float2*)o0 = make_float2(acc[mi][n][0] * i0v, acc[mi][n][1] * i1v);
            *(float2*)o1 = make_float2(acc[mi][n][2] * i0v, acc[mi][n][3] * i1v);
        }
}

// ====================================================================
extern "C" void kernel_launch(void* const* d_in, const int* in_sizes, int n_in,
                              void* d_out, int out_size)
{
    const float* x  = (const float*)d_in[0];
    const float* Wq = (const float*)d_in[1];
    const float* gq = (const float*)d_in[2];
    const float* bq = (const float*)d_in[3];
    const float* Wk = (const float*)d_in[4];
    const float* gk = (const float*)d_in[5];
    const float* bk = (const float*)d_in[6];
    const float* Wv = (const float*)d_in[7];
    const float* gv = (const float*)d_in[8];
    const float* bv = (const float*)d_in[9];
    float* out = (float*)d_out;

    cudaFuncSetAttribute(proj_hmma, cudaFuncAttributeMaxDynamicSharedMemorySize, SMSZ);
    cudaFuncSetAttribute(attn_hmma, cudaFuncAttributeMaxDynamicSharedMemorySize, SMSZ);
    cudaFuncSetAttribute(out_hmma,  cudaFuncAttributeMaxDynamicSharedMemorySize, SMSZO);

    split_w     <<< dim3(512, 3), 256 >>>(Wq, Wk, Wv);
    transpose_x <<< dim3(64, 16, 8), dim3(32, 8) >>>(x);
    proj_hmma   <<< dim3(16, 8, 24), 256, SMSZ >>>();
    stats_red   <<< dim3(COUT_, 3), 128 >>>(gq, bq, gk, bk, gv, bv);
    fin_q       <<< dim3(2, COUT_, B_), 256 >>>();
    fin_kv      <<< dim3(64, 32, 16), dim3(32, 8) >>>();
    attn_hmma   <<< dim3(16, 16, NBH_), 256, SMSZ >>>();
    red_psum    <<< 512, 256 >>>();
    out_hmma    <<< dim3(16, 1, NBH_), 256, SMSZO >>>(out);
}